// round 1
// baseline (speedup 1.0000x reference)
#include <cuda_runtime.h>
#include <math.h>
#include <stdint.h>

// Problem constants
#define PB 32
#define PN 2048
#define PH 128
#define PG4 512
#define PM (PB * PN)  // 65536 rows

// ---------------- device scratch (no allocations allowed) ----------------
__device__ float g_contrib[(size_t)PM * PG4];   // [c0 | h0 | c1 | h1] per row
__device__ float g_accum[(size_t)PM * PG4];     // aggregation numerators
__device__ float g_WiP0[PH * PG4];
__device__ float g_WhP0[PH * PG4];
__device__ float g_WiP1[PH * PG4];
__device__ float g_WhP1[PH * PG4];
__device__ float g_bP0[PG4];
__device__ float g_bP1[PG4];
__device__ float g_wr[PM];
__device__ float g_wt[PM];
__device__ float g_wf[PM];
__device__ float g_ipnew[PM];

__device__ __forceinline__ float sigf(float x) { return 1.0f / (1.0f + expf(-x)); }

// ---------------- weight permutation: WP[k, 4*idx+g] = W[k, g*128+idx] ----------------
__global__ void ip_permute(const float* __restrict__ Wi0, const float* __restrict__ Wh0,
                           const float* __restrict__ b0,
                           const float* __restrict__ Wi1, const float* __restrict__ Wh1,
                           const float* __restrict__ b1)
{
    int t = blockIdx.x * blockDim.x + threadIdx.x;
    if (t >= PH * PG4) return;
    int pc  = t & 511;
    int g   = pc & 3;
    int idx = pc >> 2;
    int k   = t >> 9;
    int src = (k << 9) + (g << 7) + idx;
    g_WiP0[t] = Wi0[src];
    g_WhP0[t] = Wh0[src];
    g_WiP1[t] = Wi1[src];
    g_WhP1[t] = Wh1[src];
    if (t < PG4) {
        int s = (g << 7) + idx;
        g_bP0[t] = b0[s];
        g_bP1[t] = b1[s];
    }
}

// ---------------- fused SGEMM + LSTM cell update ----------------
// C(M,512p) = X(M,128)*WiP + Hold(M,128)*WhP + bP, then LSTM activations.
// Tile: 128x128, BK=16, 256 threads, 8x8 microtile. Double-buffered smem.
__device__ __forceinline__ void ip_tile_load(
    float (* __restrict__ A)[128], float (* __restrict__ Bsh)[128],
    const float* __restrict__ Aglob, int astride,
    const float* __restrict__ Wglob,
    int row0, int col0, int k0,
    int ar, int ak, int bk, int bc)
{
    const float* ap = Aglob + (size_t)(row0 + ar) * astride + k0 + ak;
    float4 a0 = *(const float4*)ap;
    float4 a1 = *(const float4*)(ap + 4);
    A[ak + 0][ar] = a0.x; A[ak + 1][ar] = a0.y; A[ak + 2][ar] = a0.z; A[ak + 3][ar] = a0.w;
    A[ak + 4][ar] = a1.x; A[ak + 5][ar] = a1.y; A[ak + 6][ar] = a1.z; A[ak + 7][ar] = a1.w;
    const float* wp = Wglob + (size_t)(k0 + bk) * PG4 + col0 + bc;
    *(float4*)&Bsh[bk][bc]     = *(const float4*)wp;
    *(float4*)&Bsh[bk][bc + 4] = *(const float4*)(wp + 4);
}

__global__ __launch_bounds__(256) void ip_lstm_gemm(
    const float* __restrict__ X, int xs,
    const float* __restrict__ Hd, int hsd,
    const float* __restrict__ Cd, int cs,
    const float* __restrict__ WiP, const float* __restrict__ WhP,
    const float* __restrict__ bP,
    float* __restrict__ outC, float* __restrict__ outH)
{
    __shared__ float As[2][16][128];
    __shared__ float Bs[2][16][128];

    int tid = threadIdx.x;
    int tx = tid & 15, ty = tid >> 4;
    int row0 = blockIdx.y * 128;
    int col0 = blockIdx.x * 128;

    int ar = tid >> 1;
    int ak = (tid & 1) * 8;
    int bk = tid >> 4;
    int bc = (tid & 15) * 8;

    float acc[8][8];
#pragma unroll
    for (int i = 0; i < 8; i++)
#pragma unroll
        for (int j = 0; j < 8; j++) acc[i][j] = 0.0f;

    // preload tile 0 (X / WiP)
    ip_tile_load(As[0], Bs[0], X, xs, WiP, row0, col0, 0, ar, ak, bk, bc);
    __syncthreads();

    int ty8 = ty * 8, tx8 = tx * 8;

#pragma unroll 1
    for (int kt = 0; kt < 16; ++kt) {
        int buf = kt & 1;
        if (kt < 15) {
            int kn = kt + 1;
            if (kn < 8)
                ip_tile_load(As[buf ^ 1], Bs[buf ^ 1], X, xs, WiP, row0, col0, kn * 16,
                             ar, ak, bk, bc);
            else
                ip_tile_load(As[buf ^ 1], Bs[buf ^ 1], Hd, hsd, WhP, row0, col0, (kn - 8) * 16,
                             ar, ak, bk, bc);
        }
#pragma unroll
        for (int kk = 0; kk < 16; ++kk) {
            float4 a0 = *(const float4*)&As[buf][kk][ty8];
            float4 a1 = *(const float4*)&As[buf][kk][ty8 + 4];
            float4 bq0 = *(const float4*)&Bs[buf][kk][tx8];
            float4 bq1 = *(const float4*)&Bs[buf][kk][tx8 + 4];
            float av[8] = {a0.x, a0.y, a0.z, a0.w, a1.x, a1.y, a1.z, a1.w};
            float bv[8] = {bq0.x, bq0.y, bq0.z, bq0.w, bq1.x, bq1.y, bq1.z, bq1.w};
#pragma unroll
            for (int i = 0; i < 8; i++)
#pragma unroll
                for (int j = 0; j < 8; j++)
                    acc[i][j] = fmaf(av[i], bv[j], acc[i][j]);
        }
        __syncthreads();
    }

    // fused LSTM epilogue: thread's 8 cols = 2 hidden indices x 4 gates (i,f,g,o)
    int idx0 = (col0 + tx8) >> 2;  // global hidden index base (2 consecutive)
#pragma unroll
    for (int i = 0; i < 8; i++) {
        int row = row0 + ty8 + i;
        const float* crow = Cd + (size_t)row * cs;
#pragma unroll
        for (int p = 0; p < 2; p++) {
            int cb = col0 + tx8 + 4 * p;
            float iv = acc[i][4 * p + 0] + bP[cb + 0];
            float fv = acc[i][4 * p + 1] + bP[cb + 1];
            float gv = acc[i][4 * p + 2] + bP[cb + 2];
            float ov = acc[i][4 * p + 3] + bP[cb + 3];
            float co = crow[idx0 + p];
            float cn = sigf(fv) * co + sigf(iv) * tanhf(gv);
            float hn = sigf(ov) * tanhf(cn);
            outC[(size_t)row * PG4 + idx0 + p] = cn;
            outH[(size_t)row * PG4 + idx0 + p] = hn;
        }
    }
}

// ---------------- mask exit/raise nodes: contrib <- old state ----------------
__global__ void ip_mask(const float* __restrict__ hc0, const float* __restrict__ hh0,
                        const float* __restrict__ hc1, const float* __restrict__ hh1,
                        const int* __restrict__ exi, const int* __restrict__ rai)
{
    int b = blockIdx.x;
    int node = blockIdx.y ? rai[b] : exi[b];
    int tid = threadIdx.x;  // 128
    size_t r = (size_t)b * PN + node;
    float* dst = g_contrib + r * PG4;
    size_t rb = r * PH;
    dst[tid]       = hc0[rb + tid];
    dst[128 + tid] = hh0[rb + tid];
    dst[256 + tid] = hc1[rb + tid];
    dst[384 + tid] = hh1[rb + tid];
}

// ---------------- decision heads + edge weights + ip scatter ----------------
__global__ __launch_bounds__(256) void ip_decision(
    const float* __restrict__ Wr, const float* __restrict__ brs,
    const float* __restrict__ Wb, const float* __restrict__ bbs,
    const float* __restrict__ ipin,
    const int* __restrict__ ti, const int* __restrict__ fi, const int* __restrict__ ri,
    const int* __restrict__ exi, const int* __restrict__ rai)
{
    __shared__ float sW[2048];  // [0:1024) W_raise, [1024:2048) W_branch
    int tid = threadIdx.x;
    for (int i = tid; i < 1024; i += 256) { sW[i] = Wr[i]; sW[1024 + i] = Wb[i]; }
    __syncthreads();

    int lane = tid & 31;
    int row = blockIdx.x * 8 + (tid >> 5);
    int b = row >> 11, n = row & 2047;
    const float* crow = g_contrib + (size_t)row * PG4;

    float r0 = 0.f, r1 = 0.f, q0 = 0.f, q1 = 0.f;
#pragma unroll
    for (int t2 = 0; t2 < 4; t2++) {
        int cb = lane * 4 + t2 * 128;
        float4 v = *(const float4*)&crow[cb];
        float vv[4] = {v.x, v.y, v.z, v.w};
#pragma unroll
        for (int q = 0; q < 4; q++) {
            float w = vv[q];
            int c2 = (cb + q) * 2;
            r0 = fmaf(w, sW[c2 + 0], r0);
            r1 = fmaf(w, sW[c2 + 1], r1);
            q0 = fmaf(w, sW[1024 + c2 + 0], q0);
            q1 = fmaf(w, sW[1024 + c2 + 1], q1);
        }
    }
#pragma unroll
    for (int o = 16; o > 0; o >>= 1) {
        r0 += __shfl_xor_sync(0xffffffffu, r0, o);
        r1 += __shfl_xor_sync(0xffffffffu, r1, o);
        q0 += __shfl_xor_sync(0xffffffffu, q0, o);
        q1 += __shfl_xor_sync(0xffffffffu, q1, o);
    }

    float lr = (r0 + brs[0]) - (r1 + brs[1]);
    float p_raise = 1.0f / (1.0f + expf(-lr));
    float p_no = 1.0f - p_raise;
    if (n == exi[b] || n == rai[b]) { p_raise = 0.0f; p_no = 1.0f; }
    float lb = (q0 + bbs[0]) - (q1 + bbs[1]);
    float pb0 = 1.0f / (1.0f + expf(-lb));
    float pb1 = 1.0f - pb0;

    float ipv = ipin[row];
    float wr_ = p_raise * ipv;
    float wt_ = p_no * pb0 * ipv;
    float wf_ = p_no * pb1 * ipv;

    if (lane == 0) {
        g_wr[row] = wr_; g_wt[row] = wt_; g_wf[row] = wf_;
        int bb2 = b << 11;
        atomicAdd(&g_ipnew[bb2 + ri[row]], wr_);
        atomicAdd(&g_ipnew[bb2 + ti[row]], wt_);
        atomicAdd(&g_ipnew[bb2 + fi[row]], wf_);
    }
}

// ---------------- weighted scatter of contrib rows ----------------
__global__ __launch_bounds__(256) void ip_aggregate(
    const int* __restrict__ ti, const int* __restrict__ fi, const int* __restrict__ ri)
{
    int tid = threadIdx.x;
    int lane = tid & 31;
    int row = blockIdx.x * 8 + (tid >> 5);
    int b = row >> 11;

    float wr_ = g_wr[row], wt_ = g_wt[row], wf_ = g_wf[row];
    int tr = ri[row], tt = ti[row], tf = fi[row];

    const float* crow = g_contrib + (size_t)row * PG4;
    float4 v[4];
#pragma unroll
    for (int t2 = 0; t2 < 4; t2++) v[t2] = *(const float4*)&crow[lane * 4 + t2 * 128];

    size_t bb2 = (size_t)(b << 11);
    if (wr_ != 0.0f) {
        float* pr = g_accum + (bb2 + tr) * PG4 + lane * 4;
#pragma unroll
        for (int t2 = 0; t2 < 4; t2++) {
            float* p = pr + t2 * 128;
            atomicAdd(p + 0, v[t2].x * wr_); atomicAdd(p + 1, v[t2].y * wr_);
            atomicAdd(p + 2, v[t2].z * wr_); atomicAdd(p + 3, v[t2].w * wr_);
        }
    }
    if (wt_ != 0.0f) {
        float* pr = g_accum + (bb2 + tt) * PG4 + lane * 4;
#pragma unroll
        for (int t2 = 0; t2 < 4; t2++) {
            float* p = pr + t2 * 128;
            atomicAdd(p + 0, v[t2].x * wt_); atomicAdd(p + 1, v[t2].y * wt_);
            atomicAdd(p + 2, v[t2].z * wt_); atomicAdd(p + 3, v[t2].w * wt_);
        }
    }
    if (wf_ != 0.0f) {
        float* pr = g_accum + (bb2 + tf) * PG4 + lane * 4;
#pragma unroll
        for (int t2 = 0; t2 < 4; t2++) {
            float* p = pr + t2 * 128;
            atomicAdd(p + 0, v[t2].x * wf_); atomicAdd(p + 1, v[t2].y * wf_);
            atomicAdd(p + 2, v[t2].z * wf_); atomicAdd(p + 3, v[t2].w * wf_);
        }
    }
}

// ---------------- finalize: divide, not_done gate, pack output ----------------
__global__ void ip_finalize(
    const float* __restrict__ hc0, const float* __restrict__ hh0,
    const float* __restrict__ hc1, const float* __restrict__ hh1,
    const float* __restrict__ ipold, const int* __restrict__ slim,
    const int* __restrict__ cstep, int cs_fallback, float* __restrict__ out)
{
    int row = blockIdx.x;
    int tid = threadIdx.x;  // 128
    int b = row >> 11;
    int cs = cstep ? cstep[0] : cs_fallback;
    bool nd = cs < slim[b];
    size_t ob = (size_t)row * 513;
    if (nd) {
        float ipn = g_ipnew[row];
        float inv = 1.0f / (ipn + 1e-7f);
        const float* arow = g_accum + (size_t)row * PG4;
        out[ob + tid]       = arow[tid] * inv;
        out[ob + 128 + tid] = arow[128 + tid] * inv;
        out[ob + 256 + tid] = arow[256 + tid] * inv;
        out[ob + 384 + tid] = arow[384 + tid] * inv;
        if (tid == 0) out[ob + 512] = ipn;
    } else {
        size_t rb = (size_t)row * PH;
        out[ob + tid]       = hc0[rb + tid];
        out[ob + 128 + tid] = hh0[rb + tid];
        out[ob + 256 + tid] = hc1[rb + tid];
        out[ob + 384 + tid] = hh1[rb + tid];
        if (tid == 0) out[ob + 512] = ipold[row];
    }
}

// ---------------- host launcher ----------------
extern "C" void kernel_launch(void* const* d_in, const int* in_sizes, int n_in,
                              void* d_out, int out_size)
{
    const float* emb  = (const float*)d_in[0];
    const float* hc0  = (const float*)d_in[1];
    const float* hh0  = (const float*)d_in[2];
    const float* hc1  = (const float*)d_in[3];
    const float* hh1  = (const float*)d_in[4];
    const float* ip   = (const float*)d_in[5];
    const float* Wi0  = (const float*)d_in[6];
    const float* Wh0  = (const float*)d_in[7];
    const float* b0   = (const float*)d_in[8];
    const float* Wi1  = (const float*)d_in[9];
    const float* Wh1  = (const float*)d_in[10];
    const float* b1   = (const float*)d_in[11];
    const float* Wr   = (const float*)d_in[12];
    const float* br   = (const float*)d_in[13];
    const float* Wb   = (const float*)d_in[14];
    const float* bb   = (const float*)d_in[15];
    const int* ti     = (const int*)d_in[16];
    const int* fi     = (const int*)d_in[17];
    const int* ri     = (const int*)d_in[18];
    const int* exi    = (const int*)d_in[19];
    const int* rai    = (const int*)d_in[20];
    const int* slim   = (const int*)d_in[21];
    const int* cstep  = (n_in >= 23) ? (const int*)d_in[22] : nullptr;
    float* out = (float*)d_out;

    float *contrib, *accum, *ipnew;
    float *WiP0, *WhP0, *WiP1, *WhP1, *bP0, *bP1;
    cudaGetSymbolAddress((void**)&contrib, g_contrib);
    cudaGetSymbolAddress((void**)&accum,   g_accum);
    cudaGetSymbolAddress((void**)&ipnew,   g_ipnew);
    cudaGetSymbolAddress((void**)&WiP0,    g_WiP0);
    cudaGetSymbolAddress((void**)&WhP0,    g_WhP0);
    cudaGetSymbolAddress((void**)&WiP1,    g_WiP1);
    cudaGetSymbolAddress((void**)&WhP1,    g_WhP1);
    cudaGetSymbolAddress((void**)&bP0,     g_bP0);
    cudaGetSymbolAddress((void**)&bP1,     g_bP1);

    cudaMemsetAsync(accum, 0, sizeof(float) * (size_t)PM * PG4, 0);
    cudaMemsetAsync(ipnew, 0, sizeof(float) * (size_t)PM, 0);

    ip_permute<<<(PH * PG4 + 255) / 256, 256>>>(Wi0, Wh0, b0, Wi1, Wh1, b1);

    dim3 ggrid(4, PM / 128);
    // Layer 0: x = emb, h = hh0, c = hc0 -> contrib[0:128]=c0n, [128:256]=h0n
    ip_lstm_gemm<<<ggrid, 256>>>(emb, PH, hh0, PH, hc0, PH,
                                 WiP0, WhP0, bP0, contrib + 0, contrib + 128);
    // Layer 1: x = h0n (stride 512), h = hh1, c = hc1 -> [256:384]=c1n, [384:512]=h1n
    ip_lstm_gemm<<<ggrid, 256>>>(contrib + 128, PG4, hh1, PH, hc1, PH,
                                 WiP1, WhP1, bP1, contrib + 256, contrib + 384);

    ip_mask<<<dim3(PB, 2), 128>>>(hc0, hh0, hc1, hh1, exi, rai);

    ip_decision<<<PM / 8, 256>>>(Wr, br, Wb, bb, ip, ti, fi, ri, exi, rai);

    ip_aggregate<<<PM / 8, 256>>>(ti, fi, ri);

    ip_finalize<<<PM, 128>>>(hc0, hh0, hc1, hh1, ip, slim, cstep, 5, out);
}

// round 5
// speedup vs baseline: 1.8037x; 1.8037x over previous
#include <cuda_runtime.h>
#include <math.h>
#include <stdint.h>

// Problem constants
#define PB 32
#define PN 2048
#define PH 128
#define PG4 512
#define PM (PB * PN)   // 65536 rows
#define PK 256         // combined K = [X | H]

// ---------------- device scratch (no allocations allowed) ----------------
__device__ float g_contrib[(size_t)PM * PG4];   // [c0 | h0 | c1 | h1] per row
__device__ float g_accum[(size_t)PM * PG4];     // aggregation numerators
__device__ float g_WT0[PG4 * PK];               // B operand, layer0: [n][k], tf32-rounded
__device__ float g_WT1[PG4 * PK];               // layer1
__device__ float g_bP0[PG4];
__device__ float g_bP1[PG4];
__device__ float g_wr[PM];
__device__ float g_wt[PM];
__device__ float g_wf[PM];
__device__ float g_ipnew[PM];

// ---------------- helpers ----------------
__device__ __forceinline__ uint32_t smem_u32(const void* p) {
    uint32_t a;
    asm("{ .reg .u64 t; cvta.to.shared.u64 t, %1; cvt.u32.u64 %0, t; }" : "=r"(a) : "l"(p));
    return a;
}
__device__ __forceinline__ uint32_t f2tf32(float x) {
    uint32_t r;
    asm("cvt.rna.tf32.f32 %0, %1;" : "=r"(r) : "f"(x));
    return r;
}
__device__ __forceinline__ void mma8(float* d, const uint32_t* a, const uint32_t* b) {
    asm volatile(
        "mma.sync.aligned.m16n8k8.row.col.f32.tf32.tf32.f32 "
        "{%0,%1,%2,%3}, {%4,%5,%6,%7}, {%8,%9}, {%0,%1,%2,%3};"
        : "+f"(d[0]), "+f"(d[1]), "+f"(d[2]), "+f"(d[3])
        : "r"(a[0]), "r"(a[1]), "r"(a[2]), "r"(a[3]), "r"(b[0]), "r"(b[1]));
}
#define CP_ASYNC16(s, g) asm volatile("cp.async.cg.shared.global [%0], [%1], 16;" :: "r"(s), "l"(g))
#define CP_COMMIT() asm volatile("cp.async.commit_group;" ::: "memory")
#define CP_WAIT0() asm volatile("cp.async.wait_group 0;" ::: "memory")

__device__ __forceinline__ float sigf(float x) {
    return __fdividef(1.0f, 1.0f + __expf(-x));
}
__device__ __forceinline__ float tanhf_f(float x) {
    float xc = fminf(fmaxf(x, -15.0f), 15.0f);
    float e = __expf(2.0f * xc);
    return __fdividef(e - 1.0f, e + 1.0f);
}

// ---------------- weight prep ----------------
// Gate-column permutation: for unit u (0..127), gate g (i=0,f=1,g=2,o=3):
//   c(u,g) = (u>>2)*16 + (u&3)*2 + (g&1) + (g>>1)*8
// WT[n][k] = tf32( [Wi | Wh][k][orig_col(n)] ), K-major (contiguous k per n).
__global__ void ip_permute(const float* __restrict__ Wi0, const float* __restrict__ Wh0,
                           const float* __restrict__ b0,
                           const float* __restrict__ Wi1, const float* __restrict__ Wh1,
                           const float* __restrict__ b1)
{
    int t = blockIdx.x * 256 + threadIdx.x;    // [0, 512*256)
    int n = t >> 8;
    int k = t & 255;
    int blk = n >> 4, w = n & 15;
    int ghi = w >> 3, pos = (w & 7) >> 1, glo = w & 1;
    int u = blk * 4 + pos;
    int g = ghi * 2 + glo;
    int oc = g * 128 + u;
    float w0 = (k < 128) ? Wi0[k * PG4 + oc] : Wh0[(k - 128) * PG4 + oc];
    float w1 = (k < 128) ? Wi1[k * PG4 + oc] : Wh1[(k - 128) * PG4 + oc];
    g_WT0[t] = __uint_as_float(f2tf32(w0));
    g_WT1[t] = __uint_as_float(f2tf32(w1));
    if (k == 0) {
        g_bP0[n] = b0[oc];
        g_bP1[n] = b1[oc];
    }
}

// ---------------- tf32 mma.sync GEMM + fused LSTM epilogue ----------------
// CTA: 128 rows x 256 gate-cols. 8 warps (2 M x 4 N), warp tile 64x64.
// K = 256 in 8 chunks of 32. Smem rows padded to 36 floats (conflict-free frags).
#define A_STRIDE 36
#define A_BUF_BYTES (128 * A_STRIDE * 4)
#define B_BUF_BYTES (256 * A_STRIDE * 4)
#define SMEM_TOTAL_GEMM (2 * A_BUF_BYTES + 2 * B_BUF_BYTES)   // 110592

__global__ __launch_bounds__(256, 1) void ip_lstm_mma(
    const float* __restrict__ X, int xs,
    const float* __restrict__ Hp, int hs,
    const float* __restrict__ Cold,
    const float* __restrict__ WT, const float* __restrict__ bP,
    float* __restrict__ outC, float* __restrict__ outH)
{
    extern __shared__ char smem[];
    uint32_t* Ab[2] = { (uint32_t*)smem, (uint32_t*)(smem + A_BUF_BYTES) };
    uint32_t* Bb[2] = { (uint32_t*)(smem + 2 * A_BUF_BYTES),
                        (uint32_t*)(smem + 2 * A_BUF_BYTES + B_BUF_BYTES) };

    int tid = threadIdx.x;
    int wid = tid >> 5, lane = tid & 31;
    int wm = wid & 1, wn = wid >> 1;
    int row0 = blockIdx.y * 128;
    int col0 = blockIdx.x * 256;

    float acc[4][8][4];
#pragma unroll
    for (int mt = 0; mt < 4; mt++)
#pragma unroll
        for (int nt = 0; nt < 8; nt++)
#pragma unroll
            for (int q = 0; q < 4; q++) acc[mt][nt][q] = 0.0f;

    // bias registers (permuted layout)
    float bI[4], bF[4], bG[4], bO[4];
#pragma unroll
    for (int p = 0; p < 4; p++) {
        int c0 = col0 + wn * 64 + p * 16 + (lane & 3) * 2;
        bI[p] = bP[c0];     bF[p] = bP[c0 + 1];
        bG[p] = bP[c0 + 8]; bO[p] = bP[c0 + 9];
    }

    // prologue: chunk 0
    {
#pragma unroll
        for (int j = 0; j < 8; j++) {
            int fid = j * 256 + tid;
            int n = fid >> 3, q = fid & 7;
            uint32_t dst = smem_u32((char*)Bb[0] + n * (A_STRIDE * 4) + q * 16);
            CP_ASYNC16(dst, WT + (size_t)(col0 + n) * PK + q * 4);
        }
        CP_COMMIT();
#pragma unroll
        for (int j = 0; j < 4; j++) {
            int fid = j * 256 + tid;
            int r = fid >> 3, q = fid & 7;
            float4 v = *(const float4*)(X + (size_t)(row0 + r) * xs + q * 4);
            uint4 u4 = make_uint4(f2tf32(v.x), f2tf32(v.y), f2tf32(v.z), f2tf32(v.w));
            *(uint4*)((char*)Ab[0] + r * (A_STRIDE * 4) + q * 16) = u4;
        }
        CP_WAIT0();
        __syncthreads();
    }

    int a_base = (wm * 64 + (lane >> 2)) * A_STRIDE;
    int b_base = (wn * 64 + (lane >> 2)) * A_STRIDE;
    int kc = lane & 3;

#pragma unroll 1
    for (int ch = 0; ch < 8; ch++) {
        int buf = ch & 1;
        float4 stage[4];
        if (ch < 7) {
            int chn = ch + 1;
            int ka = (chn & 3) * 32;   // A: k within current source (X or Hp)
            int kb = chn * 32;         // B: global k within combined WT (0..255)
#pragma unroll
            for (int j = 0; j < 8; j++) {
                int fid = j * 256 + tid;
                int n = fid >> 3, q = fid & 7;
                uint32_t dst = smem_u32((char*)Bb[buf ^ 1] + n * (A_STRIDE * 4) + q * 16);
                CP_ASYNC16(dst, WT + (size_t)(col0 + n) * PK + kb + q * 4);
            }
            CP_COMMIT();
            const float* Asrc = (chn < 4) ? X : Hp;
            int astr = (chn < 4) ? xs : hs;
#pragma unroll
            for (int j = 0; j < 4; j++) {
                int fid = j * 256 + tid;
                int r = fid >> 3, q = fid & 7;
                stage[j] = *(const float4*)(Asrc + (size_t)(row0 + r) * astr + ka + q * 4);
            }
        }

        uint32_t* Abuf = Ab[buf];
        uint32_t* Bbuf = Bb[buf];
#pragma unroll
        for (int ks = 0; ks < 4; ks++) {
            int kk = ks * 8 + kc;
            uint32_t a[4][4];
#pragma unroll
            for (int mt = 0; mt < 4; mt++) {
                int rb = a_base + mt * 16 * A_STRIDE;
                a[mt][0] = Abuf[rb + kk];
                a[mt][1] = Abuf[rb + 8 * A_STRIDE + kk];
                a[mt][2] = Abuf[rb + kk + 4];
                a[mt][3] = Abuf[rb + 8 * A_STRIDE + kk + 4];
            }
            uint32_t b[8][2];
#pragma unroll
            for (int nt = 0; nt < 8; nt++) {
                int nb = b_base + nt * 8 * A_STRIDE;
                b[nt][0] = Bbuf[nb + kk];
                b[nt][1] = Bbuf[nb + kk + 4];
            }
#pragma unroll
            for (int mt = 0; mt < 4; mt++)
#pragma unroll
                for (int nt = 0; nt < 8; nt++)
                    mma8(acc[mt][nt], a[mt], b[nt]);
        }

        if (ch < 7) {
#pragma unroll
            for (int j = 0; j < 4; j++) {
                int fid = j * 256 + tid;
                int r = fid >> 3, q = fid & 7;
                float4 v = stage[j];
                uint4 u4 = make_uint4(f2tf32(v.x), f2tf32(v.y), f2tf32(v.z), f2tf32(v.w));
                *(uint4*)((char*)Ab[buf ^ 1] + r * (A_STRIDE * 4) + q * 16) = u4;
            }
            CP_WAIT0();
        }
        __syncthreads();
    }

    // ---- fused LSTM epilogue (no shuffles; thread owns all 4 gates of its units) ----
#pragma unroll
    for (int mt = 0; mt < 4; mt++) {
        int r = row0 + wm * 64 + mt * 16 + (lane >> 2);
#pragma unroll
        for (int p = 0; p < 4; p++) {
            int u = (col0 >> 2) + wn * 16 + p * 4 + (lane & 3);
            float co0 = Cold[(size_t)r * PH + u];
            float co1 = Cold[(size_t)(r + 8) * PH + u];
            float iv = acc[mt][2 * p][0] + bI[p];
            float fv = acc[mt][2 * p][1] + bF[p];
            float gv = acc[mt][2 * p + 1][0] + bG[p];
            float ov = acc[mt][2 * p + 1][1] + bO[p];
            float cn0 = sigf(fv) * co0 + sigf(iv) * tanhf_f(gv);
            float hn0 = sigf(ov) * tanhf_f(cn0);
            float iv1 = acc[mt][2 * p][2] + bI[p];
            float fv1 = acc[mt][2 * p][3] + bF[p];
            float gv1 = acc[mt][2 * p + 1][2] + bG[p];
            float ov1 = acc[mt][2 * p + 1][3] + bO[p];
            float cn1 = sigf(fv1) * co1 + sigf(iv1) * tanhf_f(gv1);
            float hn1 = sigf(ov1) * tanhf_f(cn1);

            outC[(size_t)r * PG4 + u] = cn0;
            outH[(size_t)r * PG4 + u] = hn0;
            outC[(size_t)(r + 8) * PG4 + u] = cn1;
            outH[(size_t)(r + 8) * PG4 + u] = hn1;
        }
    }
}

// ---------------- mask exit/raise nodes: contrib <- old state ----------------
__global__ void ip_mask(const float* __restrict__ hc0, const float* __restrict__ hh0,
                        const float* __restrict__ hc1, const float* __restrict__ hh1,
                        const int* __restrict__ exi, const int* __restrict__ rai)
{
    int b = blockIdx.x;
    int node = blockIdx.y ? rai[b] : exi[b];
    int tid = threadIdx.x;  // 128
    size_t r = (size_t)b * PN + node;
    float* dst = g_contrib + r * PG4;
    size_t rb = r * PH;
    dst[tid]       = hc0[rb + tid];
    dst[128 + tid] = hh0[rb + tid];
    dst[256 + tid] = hc1[rb + tid];
    dst[384 + tid] = hh1[rb + tid];
}

// ---------------- decision heads + edge weights + ip scatter ----------------
__global__ __launch_bounds__(256) void ip_decision(
    const float* __restrict__ Wr, const float* __restrict__ brs,
    const float* __restrict__ Wb, const float* __restrict__ bbs,
    const float* __restrict__ ipin,
    const int* __restrict__ ti, const int* __restrict__ fi, const int* __restrict__ ri,
    const int* __restrict__ exi, const int* __restrict__ rai)
{
    __shared__ float sW[2048];
    int tid = threadIdx.x;
    for (int i = tid; i < 1024; i += 256) { sW[i] = Wr[i]; sW[1024 + i] = Wb[i]; }
    __syncthreads();

    int lane = tid & 31;
    int row = blockIdx.x * 8 + (tid >> 5);
    int b = row >> 11, n = row & 2047;
    const float* crow = g_contrib + (size_t)row * PG4;

    float r0 = 0.f, r1 = 0.f, q0 = 0.f, q1 = 0.f;
#pragma unroll
    for (int t2 = 0; t2 < 4; t2++) {
        int cb = lane * 4 + t2 * 128;
        float4 v = *(const float4*)&crow[cb];
        float vv[4] = {v.x, v.y, v.z, v.w};
#pragma unroll
        for (int q = 0; q < 4; q++) {
            float w = vv[q];
            int c2 = (cb + q) * 2;
            r0 = fmaf(w, sW[c2 + 0], r0);
            r1 = fmaf(w, sW[c2 + 1], r1);
            q0 = fmaf(w, sW[1024 + c2 + 0], q0);
            q1 = fmaf(w, sW[1024 + c2 + 1], q1);
        }
    }
#pragma unroll
    for (int o = 16; o > 0; o >>= 1) {
        r0 += __shfl_xor_sync(0xffffffffu, r0, o);
        r1 += __shfl_xor_sync(0xffffffffu, r1, o);
        q0 += __shfl_xor_sync(0xffffffffu, q0, o);
        q1 += __shfl_xor_sync(0xffffffffu, q1, o);
    }

    float lr = (r0 + brs[0]) - (r1 + brs[1]);
    float p_raise = 1.0f / (1.0f + expf(-lr));
    float p_no = 1.0f - p_raise;
    if (n == exi[b] || n == rai[b]) { p_raise = 0.0f; p_no = 1.0f; }
    float lb = (q0 + bbs[0]) - (q1 + bbs[1]);
    float pb0 = 1.0f / (1.0f + expf(-lb));
    float pb1 = 1.0f - pb0;

    float ipv = ipin[row];
    float wr_ = p_raise * ipv;
    float wt_ = p_no * pb0 * ipv;
    float wf_ = p_no * pb1 * ipv;

    if (lane == 0) {
        g_wr[row] = wr_; g_wt[row] = wt_; g_wf[row] = wf_;
        int bb2 = b << 11;
        atomicAdd(&g_ipnew[bb2 + ri[row]], wr_);
        atomicAdd(&g_ipnew[bb2 + ti[row]], wt_);
        atomicAdd(&g_ipnew[bb2 + fi[row]], wf_);
    }
}

// ---------------- weighted scatter of contrib rows ----------------
__global__ __launch_bounds__(256) void ip_aggregate(
    const int* __restrict__ ti, const int* __restrict__ fi, const int* __restrict__ ri)
{
    int tid = threadIdx.x;
    int lane = tid & 31;
    int row = blockIdx.x * 8 + (tid >> 5);
    int b = row >> 11;

    float wr_ = g_wr[row], wt_ = g_wt[row], wf_ = g_wf[row];
    int tr = ri[row], tt = ti[row], tf = fi[row];

    const float* crow = g_contrib + (size_t)row * PG4;
    float4 v[4];
#pragma unroll
    for (int t2 = 0; t2 < 4; t2++) v[t2] = *(const float4*)&crow[lane * 4 + t2 * 128];

    size_t bb2 = (size_t)(b << 11);
    if (wr_ != 0.0f) {
        float* pr = g_accum + (bb2 + tr) * PG4 + lane * 4;
#pragma unroll
        for (int t2 = 0; t2 < 4; t2++) {
            float* p = pr + t2 * 128;
            atomicAdd(p + 0, v[t2].x * wr_); atomicAdd(p + 1, v[t2].y * wr_);
            atomicAdd(p + 2, v[t2].z * wr_); atomicAdd(p + 3, v[t2].w * wr_);
        }
    }
    if (wt_ != 0.0f) {
        float* pr = g_accum + (bb2 + tt) * PG4 + lane * 4;
#pragma unroll
        for (int t2 = 0; t2 < 4; t2++) {
            float* p = pr + t2 * 128;
            atomicAdd(p + 0, v[t2].x * wt_); atomicAdd(p + 1, v[t2].y * wt_);
            atomicAdd(p + 2, v[t2].z * wt_); atomicAdd(p + 3, v[t2].w * wt_);
        }
    }
    if (wf_ != 0.0f) {
        float* pr = g_accum + (bb2 + tf) * PG4 + lane * 4;
#pragma unroll
        for (int t2 = 0; t2 < 4; t2++) {
            float* p = pr + t2 * 128;
            atomicAdd(p + 0, v[t2].x * wf_); atomicAdd(p + 1, v[t2].y * wf_);
            atomicAdd(p + 2, v[t2].z * wf_); atomicAdd(p + 3, v[t2].w * wf_);
        }
    }
}

// ---------------- finalize: divide, not_done gate, pack output ----------------
__global__ void ip_finalize(
    const float* __restrict__ hc0, const float* __restrict__ hh0,
    const float* __restrict__ hc1, const float* __restrict__ hh1,
    const float* __restrict__ ipold, const int* __restrict__ slim,
    const int* __restrict__ cstep, int cs_fallback, float* __restrict__ out)
{
    int row = blockIdx.x;
    int tid = threadIdx.x;  // 128
    int b = row >> 11;
    int cs = cstep ? cstep[0] : cs_fallback;
    bool nd = cs < slim[b];
    size_t ob = (size_t)row * 513;
    if (nd) {
        float ipn = g_ipnew[row];
        float inv = 1.0f / (ipn + 1e-7f);
        const float* arow = g_accum + (size_t)row * PG4;
        out[ob + tid]       = arow[tid] * inv;
        out[ob + 128 + tid] = arow[128 + tid] * inv;
        out[ob + 256 + tid] = arow[256 + tid] * inv;
        out[ob + 384 + tid] = arow[384 + tid] * inv;
        if (tid == 0) out[ob + 512] = ipn;
    } else {
        size_t rb = (size_t)row * PH;
        out[ob + tid]       = hc0[rb + tid];
        out[ob + 128 + tid] = hh0[rb + tid];
        out[ob + 256 + tid] = hc1[rb + tid];
        out[ob + 384 + tid] = hh1[rb + tid];
        if (tid == 0) out[ob + 512] = ipold[row];
    }
}

// ---------------- host launcher ----------------
extern "C" void kernel_launch(void* const* d_in, const int* in_sizes, int n_in,
                              void* d_out, int out_size)
{
    const float* emb  = (const float*)d_in[0];
    const float* hc0  = (const float*)d_in[1];
    const float* hh0  = (const float*)d_in[2];
    const float* hc1  = (const float*)d_in[3];
    const float* hh1  = (const float*)d_in[4];
    const float* ip   = (const float*)d_in[5];
    const float* Wi0  = (const float*)d_in[6];
    const float* Wh0  = (const float*)d_in[7];
    const float* b0   = (const float*)d_in[8];
    const float* Wi1  = (const float*)d_in[9];
    const float* Wh1  = (const float*)d_in[10];
    const float* b1   = (const float*)d_in[11];
    const float* Wr   = (const float*)d_in[12];
    const float* br   = (const float*)d_in[13];
    const float* Wb   = (const float*)d_in[14];
    const float* bb   = (const float*)d_in[15];
    const int* ti     = (const int*)d_in[16];
    const int* fi     = (const int*)d_in[17];
    const int* ri     = (const int*)d_in[18];
    const int* exi    = (const int*)d_in[19];
    const int* rai    = (const int*)d_in[20];
    const int* slim   = (const int*)d_in[21];
    const int* cstep  = (n_in >= 23) ? (const int*)d_in[22] : nullptr;
    float* out = (float*)d_out;

    float *contrib, *accum, *ipnew, *WT0, *WT1, *bP0, *bP1;
    cudaGetSymbolAddress((void**)&contrib, g_contrib);
    cudaGetSymbolAddress((void**)&accum,   g_accum);
    cudaGetSymbolAddress((void**)&ipnew,   g_ipnew);
    cudaGetSymbolAddress((void**)&WT0,     g_WT0);
    cudaGetSymbolAddress((void**)&WT1,     g_WT1);
    cudaGetSymbolAddress((void**)&bP0,     g_bP0);
    cudaGetSymbolAddress((void**)&bP1,     g_bP1);

    cudaFuncSetAttribute(ip_lstm_mma,
                         cudaFuncAttributeMaxDynamicSharedMemorySize, SMEM_TOTAL_GEMM);

    cudaMemsetAsync(accum, 0, sizeof(float) * (size_t)PM * PG4, 0);
    cudaMemsetAsync(ipnew, 0, sizeof(float) * (size_t)PM, 0);

    ip_permute<<<512, 256>>>(Wi0, Wh0, b0, Wi1, Wh1, b1);

    dim3 ggrid(2, PM / 128);
    // Layer 0: x = emb (stride 128), h = hh0, c = hc0 -> contrib[0:128]=c0n, [128:256]=h0n
    ip_lstm_mma<<<ggrid, 256, SMEM_TOTAL_GEMM>>>(
        emb, PH, hh0, PH, hc0, WT0, bP0, contrib + 0, contrib + 128);
    // Layer 1: x = h0n (stride 512), h = hh1, c = hc1 -> [256:384]=c1n, [384:512]=h1n
    ip_lstm_mma<<<ggrid, 256, SMEM_TOTAL_GEMM>>>(
        contrib + 128, PG4, hh1, PH, hc1, WT1, bP1, contrib + 256, contrib + 384);

    ip_mask<<<dim3(PB, 2), 128>>>(hc0, hh0, hc1, hh1, exi, rai);

    ip_decision<<<PM / 8, 256>>>(Wr, br, Wb, bb, ip, ti, fi, ri, exi, rai);

    ip_aggregate<<<PM / 8, 256>>>(ti, fi, ri);

    ip_finalize<<<PM, 128>>>(hc0, hh0, hc1, hh1, ip, slim, cstep, 5, out);
}

// round 6
// speedup vs baseline: 2.5505x; 1.4141x over previous
#include <cuda_runtime.h>
#include <math.h>
#include <stdint.h>

// Problem constants
#define PB 32
#define PN 2048
#define PH 128
#define PG4 512
#define PM (PB * PN)   // 65536 rows
#define PK 256         // combined K = [X | H]

// ---------------- device scratch (no allocations allowed) ----------------
__device__ float g_contrib[(size_t)PM * PG4];   // [c0 | h0 | c1 | h1] per row
__device__ float g_accum[(size_t)PM * PG4];     // aggregation numerators
__device__ float g_WT0[PG4 * PK];               // B operand, layer0: [n][k], tf32-rounded
__device__ float g_WT1[PG4 * PK];               // layer1
__device__ float g_bP0[PG4];
__device__ float g_bP1[PG4];
__device__ float g_ipnew[PM];

// ---------------- helpers ----------------
__device__ __forceinline__ uint32_t smem_u32(const void* p) {
    uint32_t a;
    asm("{ .reg .u64 t; cvta.to.shared.u64 t, %1; cvt.u32.u64 %0, t; }" : "=r"(a) : "l"(p));
    return a;
}
__device__ __forceinline__ uint32_t f2tf32(float x) {
    uint32_t r;
    asm("cvt.rna.tf32.f32 %0, %1;" : "=r"(r) : "f"(x));
    return r;
}
__device__ __forceinline__ void mma8(float* d, const uint32_t* a, const uint32_t* b) {
    asm volatile(
        "mma.sync.aligned.m16n8k8.row.col.f32.tf32.tf32.f32 "
        "{%0,%1,%2,%3}, {%4,%5,%6,%7}, {%8,%9}, {%0,%1,%2,%3};"
        : "+f"(d[0]), "+f"(d[1]), "+f"(d[2]), "+f"(d[3])
        : "r"(a[0]), "r"(a[1]), "r"(a[2]), "r"(a[3]), "r"(b[0]), "r"(b[1]));
}
__device__ __forceinline__ void red4(float* p, float a, float b, float c, float d) {
    asm volatile("red.global.add.v4.f32 [%0], {%1,%2,%3,%4};"
                 :: "l"(p), "f"(a), "f"(b), "f"(c), "f"(d) : "memory");
}
#define CP_ASYNC16(s, g) asm volatile("cp.async.cg.shared.global [%0], [%1], 16;" :: "r"(s), "l"(g))
#define CP_COMMIT() asm volatile("cp.async.commit_group;" ::: "memory")
#define CP_WAIT0() asm volatile("cp.async.wait_group 0;" ::: "memory")

__device__ __forceinline__ float sigf(float x) {
    return __fdividef(1.0f, 1.0f + __expf(-x));
}
__device__ __forceinline__ float tanhf_f(float x) {
    float xc = fminf(fmaxf(x, -15.0f), 15.0f);
    float e = __expf(2.0f * xc);
    return __fdividef(e - 1.0f, e + 1.0f);
}

// ---------------- weight prep (split into 3 launches so gemm0 is ncu launch #5) ----
// Gate-column permutation: for unit u (0..127), gate g (i=0,f=1,g=2,o=3):
//   c(u,g) = (u>>2)*16 + (u&3)*2 + (g&1) + (g>>1)*8
__device__ __forceinline__ int perm_oc(int n) {
    int blk = n >> 4, w = n & 15;
    int ghi = w >> 3, pos = (w & 7) >> 1, glo = w & 1;
    int u = blk * 4 + pos;
    int g = ghi * 2 + glo;
    return g * 128 + u;
}
__global__ void ip_permW(const float* __restrict__ Wi, const float* __restrict__ Wh,
                         float* __restrict__ WT)
{
    int t = blockIdx.x * 256 + threadIdx.x;    // [0, 512*256)
    int n = t >> 8;
    int k = t & 255;
    int oc = perm_oc(n);
    float w = (k < 128) ? Wi[k * PG4 + oc] : Wh[(k - 128) * PG4 + oc];
    WT[t] = __uint_as_float(f2tf32(w));
}
__global__ void ip_permB(const float* __restrict__ b0, const float* __restrict__ b1)
{
    int n = blockIdx.x * 256 + threadIdx.x;    // [0, 512)
    int oc = perm_oc(n);
    g_bP0[n] = b0[oc];
    g_bP1[n] = b1[oc];
}

// ---------------- tf32 mma.sync GEMM + fused LSTM epilogue ----------------
// CTA: 128 rows x 256 gate-cols. 8 warps (2 M x 4 N), warp tile 64x64.
// K = 256 in 8 chunks of 32. Smem rows padded to 36 floats (conflict-free frags).
#define A_STRIDE 36
#define A_BUF_BYTES (128 * A_STRIDE * 4)
#define B_BUF_BYTES (256 * A_STRIDE * 4)
#define SMEM_TOTAL_GEMM (2 * A_BUF_BYTES + 2 * B_BUF_BYTES)   // 110592

__global__ __launch_bounds__(256, 1) void ip_lstm_mma(
    const float* __restrict__ X, int xs,
    const float* __restrict__ Hp, int hs,
    const float* __restrict__ Cold,
    const float* __restrict__ WT, const float* __restrict__ bP,
    float* __restrict__ outC, float* __restrict__ outH)
{
    extern __shared__ char smem[];
    uint32_t* Ab[2] = { (uint32_t*)smem, (uint32_t*)(smem + A_BUF_BYTES) };
    uint32_t* Bb[2] = { (uint32_t*)(smem + 2 * A_BUF_BYTES),
                        (uint32_t*)(smem + 2 * A_BUF_BYTES + B_BUF_BYTES) };

    int tid = threadIdx.x;
    int wid = tid >> 5, lane = tid & 31;
    int wm = wid & 1, wn = wid >> 1;
    int row0 = blockIdx.y * 128;
    int col0 = blockIdx.x * 256;

    float acc[4][8][4];
#pragma unroll
    for (int mt = 0; mt < 4; mt++)
#pragma unroll
        for (int nt = 0; nt < 8; nt++)
#pragma unroll
            for (int q = 0; q < 4; q++) acc[mt][nt][q] = 0.0f;

    // bias registers (permuted layout)
    float bI[4], bF[4], bG[4], bO[4];
#pragma unroll
    for (int p = 0; p < 4; p++) {
        int c0 = col0 + wn * 64 + p * 16 + (lane & 3) * 2;
        bI[p] = bP[c0];     bF[p] = bP[c0 + 1];
        bG[p] = bP[c0 + 8]; bO[p] = bP[c0 + 9];
    }

    // prologue: chunk 0
    {
#pragma unroll
        for (int j = 0; j < 8; j++) {
            int fid = j * 256 + tid;
            int n = fid >> 3, q = fid & 7;
            uint32_t dst = smem_u32((char*)Bb[0] + n * (A_STRIDE * 4) + q * 16);
            CP_ASYNC16(dst, WT + (size_t)(col0 + n) * PK + q * 4);
        }
        CP_COMMIT();
#pragma unroll
        for (int j = 0; j < 4; j++) {
            int fid = j * 256 + tid;
            int r = fid >> 3, q = fid & 7;
            float4 v = *(const float4*)(X + (size_t)(row0 + r) * xs + q * 4);
            uint4 u4 = make_uint4(f2tf32(v.x), f2tf32(v.y), f2tf32(v.z), f2tf32(v.w));
            *(uint4*)((char*)Ab[0] + r * (A_STRIDE * 4) + q * 16) = u4;
        }
        CP_WAIT0();
        __syncthreads();
    }

    int a_base = (wm * 64 + (lane >> 2)) * A_STRIDE;
    int b_base = (wn * 64 + (lane >> 2)) * A_STRIDE;
    int kc = lane & 3;

#pragma unroll 1
    for (int ch = 0; ch < 8; ch++) {
        int buf = ch & 1;
        float4 stage[4];
        if (ch < 7) {
            int chn = ch + 1;
            int ka = (chn & 3) * 32;   // A: k within current source (X or Hp)
            int kb = chn * 32;         // B: global k within combined WT (0..255)
#pragma unroll
            for (int j = 0; j < 8; j++) {
                int fid = j * 256 + tid;
                int n = fid >> 3, q = fid & 7;
                uint32_t dst = smem_u32((char*)Bb[buf ^ 1] + n * (A_STRIDE * 4) + q * 16);
                CP_ASYNC16(dst, WT + (size_t)(col0 + n) * PK + kb + q * 4);
            }
            CP_COMMIT();
            const float* Asrc = (chn < 4) ? X : Hp;
            int astr = (chn < 4) ? xs : hs;
#pragma unroll
            for (int j = 0; j < 4; j++) {
                int fid = j * 256 + tid;
                int r = fid >> 3, q = fid & 7;
                stage[j] = *(const float4*)(Asrc + (size_t)(row0 + r) * astr + ka + q * 4);
            }
        }

        uint32_t* Abuf = Ab[buf];
        uint32_t* Bbuf = Bb[buf];
#pragma unroll
        for (int ks = 0; ks < 4; ks++) {
            int kk = ks * 8 + kc;
            uint32_t a[4][4];
#pragma unroll
            for (int mt = 0; mt < 4; mt++) {
                int rb = a_base + mt * 16 * A_STRIDE;
                a[mt][0] = Abuf[rb + kk];
                a[mt][1] = Abuf[rb + 8 * A_STRIDE + kk];
                a[mt][2] = Abuf[rb + kk + 4];
                a[mt][3] = Abuf[rb + 8 * A_STRIDE + kk + 4];
            }
            uint32_t b[8][2];
#pragma unroll
            for (int nt = 0; nt < 8; nt++) {
                int nb = b_base + nt * 8 * A_STRIDE;
                b[nt][0] = Bbuf[nb + kk];
                b[nt][1] = Bbuf[nb + kk + 4];
            }
#pragma unroll
            for (int mt = 0; mt < 4; mt++)
#pragma unroll
                for (int nt = 0; nt < 8; nt++)
                    mma8(acc[mt][nt], a[mt], b[nt]);
        }

        if (ch < 7) {
#pragma unroll
            for (int j = 0; j < 4; j++) {
                int fid = j * 256 + tid;
                int r = fid >> 3, q = fid & 7;
                float4 v = stage[j];
                uint4 u4 = make_uint4(f2tf32(v.x), f2tf32(v.y), f2tf32(v.z), f2tf32(v.w));
                *(uint4*)((char*)Ab[buf ^ 1] + r * (A_STRIDE * 4) + q * 16) = u4;
            }
            CP_WAIT0();
        }
        __syncthreads();
    }

    // ---- fused LSTM epilogue (no shuffles; thread owns all 4 gates of its units) ----
#pragma unroll
    for (int mt = 0; mt < 4; mt++) {
        int r = row0 + wm * 64 + mt * 16 + (lane >> 2);
#pragma unroll
        for (int p = 0; p < 4; p++) {
            int u = (col0 >> 2) + wn * 16 + p * 4 + (lane & 3);
            float co0 = Cold[(size_t)r * PH + u];
            float co1 = Cold[(size_t)(r + 8) * PH + u];
            float iv = acc[mt][2 * p][0] + bI[p];
            float fv = acc[mt][2 * p][1] + bF[p];
            float gv = acc[mt][2 * p + 1][0] + bG[p];
            float ov = acc[mt][2 * p + 1][1] + bO[p];
            float cn0 = sigf(fv) * co0 + sigf(iv) * tanhf_f(gv);
            float hn0 = sigf(ov) * tanhf_f(cn0);
            float iv1 = acc[mt][2 * p][2] + bI[p];
            float fv1 = acc[mt][2 * p][3] + bF[p];
            float gv1 = acc[mt][2 * p + 1][2] + bG[p];
            float ov1 = acc[mt][2 * p + 1][3] + bO[p];
            float cn1 = sigf(fv1) * co1 + sigf(iv1) * tanhf_f(gv1);
            float hn1 = sigf(ov1) * tanhf_f(cn1);

            outC[(size_t)r * PG4 + u] = cn0;
            outH[(size_t)r * PG4 + u] = hn0;
            outC[(size_t)(r + 8) * PG4 + u] = cn1;
            outH[(size_t)(r + 8) * PG4 + u] = hn1;
        }
    }
}

// ---------------- mask exit/raise nodes: contrib <- old state ----------------
__global__ void ip_mask(const float* __restrict__ hc0, const float* __restrict__ hh0,
                        const float* __restrict__ hc1, const float* __restrict__ hh1,
                        const int* __restrict__ exi, const int* __restrict__ rai)
{
    int b = blockIdx.x;
    int node = blockIdx.y ? rai[b] : exi[b];
    int tid = threadIdx.x;  // 128
    size_t r = (size_t)b * PN + node;
    float* dst = g_contrib + r * PG4;
    size_t rb = r * PH;
    dst[tid]       = hc0[rb + tid];
    dst[128 + tid] = hh0[rb + tid];
    dst[256 + tid] = hc1[rb + tid];
    dst[384 + tid] = hh1[rb + tid];
}

// ---------------- FUSED decision heads + weighted scatter (one contrib pass) -----
__global__ __launch_bounds__(256) void ip_decagg(
    const float* __restrict__ Wr, const float* __restrict__ brs,
    const float* __restrict__ Wb, const float* __restrict__ bbs,
    const float* __restrict__ ipin,
    const int* __restrict__ ti, const int* __restrict__ fi, const int* __restrict__ ri,
    const int* __restrict__ exi, const int* __restrict__ rai,
    const int* __restrict__ slim, const int* __restrict__ cstep, int cs_fallback)
{
    __shared__ float sW[2048];  // [0:1024) W_raise, [1024:2048) W_branch
    int tid = threadIdx.x;
    for (int i = tid; i < 1024; i += 256) { sW[i] = Wr[i]; sW[1024 + i] = Wb[i]; }
    __syncthreads();

    int lane = tid & 31;
    int row = blockIdx.x * 8 + (tid >> 5);
    int b = row >> 11, n = row & 2047;

    // done batches contribute nothing the output reads — skip entirely
    int cs = cstep ? cstep[0] : cs_fallback;
    if (cs >= slim[b]) return;

    const float* crow = g_contrib + (size_t)row * PG4;
    float4 v[4];
#pragma unroll
    for (int t2 = 0; t2 < 4; t2++) v[t2] = *(const float4*)&crow[lane * 4 + t2 * 128];

    float r0 = 0.f, r1 = 0.f, q0 = 0.f, q1 = 0.f;
#pragma unroll
    for (int t2 = 0; t2 < 4; t2++) {
        int cb = lane * 4 + t2 * 128;
        float vv[4] = {v[t2].x, v[t2].y, v[t2].z, v[t2].w};
#pragma unroll
        for (int q = 0; q < 4; q++) {
            float w = vv[q];
            int c2 = (cb + q) * 2;
            r0 = fmaf(w, sW[c2 + 0], r0);
            r1 = fmaf(w, sW[c2 + 1], r1);
            q0 = fmaf(w, sW[1024 + c2 + 0], q0);
            q1 = fmaf(w, sW[1024 + c2 + 1], q1);
        }
    }
#pragma unroll
    for (int o = 16; o > 0; o >>= 1) {
        r0 += __shfl_xor_sync(0xffffffffu, r0, o);
        r1 += __shfl_xor_sync(0xffffffffu, r1, o);
        q0 += __shfl_xor_sync(0xffffffffu, q0, o);
        q1 += __shfl_xor_sync(0xffffffffu, q1, o);
    }

    float lr = (r0 + brs[0]) - (r1 + brs[1]);
    float p_raise = 1.0f / (1.0f + expf(-lr));
    float p_no = 1.0f - p_raise;
    if (n == exi[b] || n == rai[b]) { p_raise = 0.0f; p_no = 1.0f; }
    float lb = (q0 + bbs[0]) - (q1 + bbs[1]);
    float pb0 = 1.0f / (1.0f + expf(-lb));
    float pb1 = 1.0f - pb0;

    float ipv = ipin[row];
    float wr_ = p_raise * ipv;
    float wt_ = p_no * pb0 * ipv;
    float wf_ = p_no * pb1 * ipv;

    int tr = ri[row], tt = ti[row], tf = fi[row];
    if (lane == 0) {
        int bb2 = b << 11;
        atomicAdd(&g_ipnew[bb2 + tr], wr_);
        atomicAdd(&g_ipnew[bb2 + tt], wt_);
        atomicAdd(&g_ipnew[bb2 + tf], wf_);
    }

    size_t bb2 = (size_t)(b << 11);
    if (wr_ != 0.0f) {
        float* pr = g_accum + (bb2 + tr) * PG4 + lane * 4;
#pragma unroll
        for (int t2 = 0; t2 < 4; t2++)
            red4(pr + t2 * 128, v[t2].x * wr_, v[t2].y * wr_, v[t2].z * wr_, v[t2].w * wr_);
    }
    if (wt_ != 0.0f) {
        float* pr = g_accum + (bb2 + tt) * PG4 + lane * 4;
#pragma unroll
        for (int t2 = 0; t2 < 4; t2++)
            red4(pr + t2 * 128, v[t2].x * wt_, v[t2].y * wt_, v[t2].z * wt_, v[t2].w * wt_);
    }
    if (wf_ != 0.0f) {
        float* pr = g_accum + (bb2 + tf) * PG4 + lane * 4;
#pragma unroll
        for (int t2 = 0; t2 < 4; t2++)
            red4(pr + t2 * 128, v[t2].x * wf_, v[t2].y * wf_, v[t2].z * wf_, v[t2].w * wf_);
    }
}

// ---------------- finalize: divide, not_done gate, pack output ----------------
__global__ void ip_finalize(
    const float* __restrict__ hc0, const float* __restrict__ hh0,
    const float* __restrict__ hc1, const float* __restrict__ hh1,
    const float* __restrict__ ipold, const int* __restrict__ slim,
    const int* __restrict__ cstep, int cs_fallback, float* __restrict__ out)
{
    int row = blockIdx.x;
    int tid = threadIdx.x;  // 128
    int b = row >> 11;
    int cs = cstep ? cstep[0] : cs_fallback;
    bool nd = cs < slim[b];
    size_t ob = (size_t)row * 513;
    if (nd) {
        float ipn = g_ipnew[row];
        float inv = 1.0f / (ipn + 1e-7f);
        const float* arow = g_accum + (size_t)row * PG4;
        out[ob + tid]       = arow[tid] * inv;
        out[ob + 128 + tid] = arow[128 + tid] * inv;
        out[ob + 256 + tid] = arow[256 + tid] * inv;
        out[ob + 384 + tid] = arow[384 + tid] * inv;
        if (tid == 0) out[ob + 512] = ipn;
    } else {
        size_t rb = (size_t)row * PH;
        out[ob + tid]       = hc0[rb + tid];
        out[ob + 128 + tid] = hh0[rb + tid];
        out[ob + 256 + tid] = hc1[rb + tid];
        out[ob + 384 + tid] = hh1[rb + tid];
        if (tid == 0) out[ob + 512] = ipold[row];
    }
}

// ---------------- host launcher ----------------
extern "C" void kernel_launch(void* const* d_in, const int* in_sizes, int n_in,
                              void* d_out, int out_size)
{
    const float* emb  = (const float*)d_in[0];
    const float* hc0  = (const float*)d_in[1];
    const float* hh0  = (const float*)d_in[2];
    const float* hc1  = (const float*)d_in[3];
    const float* hh1  = (const float*)d_in[4];
    const float* ip   = (const float*)d_in[5];
    const float* Wi0  = (const float*)d_in[6];
    const float* Wh0  = (const float*)d_in[7];
    const float* b0   = (const float*)d_in[8];
    const float* Wi1  = (const float*)d_in[9];
    const float* Wh1  = (const float*)d_in[10];
    const float* b1   = (const float*)d_in[11];
    const float* Wr   = (const float*)d_in[12];
    const float* br   = (const float*)d_in[13];
    const float* Wb   = (const float*)d_in[14];
    const float* bb   = (const float*)d_in[15];
    const int* ti     = (const int*)d_in[16];
    const int* fi     = (const int*)d_in[17];
    const int* ri     = (const int*)d_in[18];
    const int* exi    = (const int*)d_in[19];
    const int* rai    = (const int*)d_in[20];
    const int* slim   = (const int*)d_in[21];
    const int* cstep  = (n_in >= 23) ? (const int*)d_in[22] : nullptr;
    float* out = (float*)d_out;

    float *contrib, *accum, *ipnew, *WT0, *WT1, *bP0, *bP1;
    cudaGetSymbolAddress((void**)&contrib, g_contrib);
    cudaGetSymbolAddress((void**)&accum,   g_accum);
    cudaGetSymbolAddress((void**)&ipnew,   g_ipnew);
    cudaGetSymbolAddress((void**)&WT0,     g_WT0);
    cudaGetSymbolAddress((void**)&WT1,     g_WT1);
    cudaGetSymbolAddress((void**)&bP0,     g_bP0);
    cudaGetSymbolAddress((void**)&bP1,     g_bP1);

    cudaFuncSetAttribute(ip_lstm_mma,
                         cudaFuncAttributeMaxDynamicSharedMemorySize, SMEM_TOTAL_GEMM);

    // launches 0-4 (so ncu -s 5 -c 1 lands on gemm0)
    cudaMemsetAsync(accum, 0, sizeof(float) * (size_t)PM * PG4, 0);   // 0
    cudaMemsetAsync(ipnew, 0, sizeof(float) * (size_t)PM, 0);         // 1
    ip_permW<<<512, 256>>>(Wi0, Wh0, WT0);                            // 2
    ip_permW<<<512, 256>>>(Wi1, Wh1, WT1);                            // 3
    ip_permB<<<2, 256>>>(b0, b1);                                     // 4

    dim3 ggrid(2, PM / 128);
    // Layer 0 (launch 5: ncu target): x = emb, h = hh0, c = hc0
    ip_lstm_mma<<<ggrid, 256, SMEM_TOTAL_GEMM>>>(
        emb, PH, hh0, PH, hc0, WT0, bP0, contrib + 0, contrib + 128);
    // Layer 1: x = h0n (stride 512), h = hh1, c = hc1
    ip_lstm_mma<<<ggrid, 256, SMEM_TOTAL_GEMM>>>(
        contrib + 128, PG4, hh1, PH, hc1, WT1, bP1, contrib + 256, contrib + 384);

    ip_mask<<<dim3(PB, 2), 128>>>(hc0, hh0, hc1, hh1, exi, rai);

    ip_decagg<<<PM / 8, 256>>>(Wr, br, Wb, bb, ip, ti, fi, ri, exi, rai,
                               slim, cstep, 5);

    ip_finalize<<<PM, 128>>>(hc0, hh0, hc1, hh1, ip, slim, cstep, 5, out);
}

// round 7
// speedup vs baseline: 2.5867x; 1.0142x over previous
#include <cuda_runtime.h>
#include <math.h>
#include <stdint.h>

// Problem constants
#define PB 32
#define PN 2048
#define PH 128
#define PG4 512
#define PM (PB * PN)   // 65536 rows
#define PK 256         // combined K = [X | H]

// ---------------- device scratch (no allocations allowed) ----------------
__device__ float g_contrib[(size_t)PM * PG4];   // [c0 | h0 | c1 | h1] per row
__device__ float g_accum[(size_t)PM * PG4];     // aggregation numerators
__device__ float g_WT0[PG4 * PK];               // B operand, layer0: [n][k], tf32-rounded
__device__ float g_WT1[PG4 * PK];               // layer1
__device__ float g_bP0[PG4];
__device__ float g_bP1[PG4];
__device__ float g_ipnew[PM];

// ---------------- helpers ----------------
__device__ __forceinline__ uint32_t smem_u32(const void* p) {
    uint32_t a;
    asm("{ .reg .u64 t; cvta.to.shared.u64 t, %1; cvt.u32.u64 %0, t; }" : "=r"(a) : "l"(p));
    return a;
}
__device__ __forceinline__ uint32_t f2tf32(float x) {
    uint32_t r;
    asm("cvt.rna.tf32.f32 %0, %1;" : "=r"(r) : "f"(x));
    return r;
}
__device__ __forceinline__ void mma8(float* d, const uint32_t* a, const uint32_t* b) {
    asm volatile(
        "mma.sync.aligned.m16n8k8.row.col.f32.tf32.tf32.f32 "
        "{%0,%1,%2,%3}, {%4,%5,%6,%7}, {%8,%9}, {%0,%1,%2,%3};"
        : "+f"(d[0]), "+f"(d[1]), "+f"(d[2]), "+f"(d[3])
        : "r"(a[0]), "r"(a[1]), "r"(a[2]), "r"(a[3]), "r"(b[0]), "r"(b[1]));
}
__device__ __forceinline__ void red4(float* p, float a, float b, float c, float d) {
    asm volatile("red.global.add.v4.f32 [%0], {%1,%2,%3,%4};"
                 :: "l"(p), "f"(a), "f"(b), "f"(c), "f"(d) : "memory");
}
#define CP_ASYNC16(s, g) asm volatile("cp.async.cg.shared.global [%0], [%1], 16;" :: "r"(s), "l"(g))
#define CP_COMMIT() asm volatile("cp.async.commit_group;" ::: "memory")
#define CP_WAIT0() asm volatile("cp.async.wait_group 0;" ::: "memory")

__device__ __forceinline__ float sigf(float x) {
    return __fdividef(1.0f, 1.0f + __expf(-x));
}
__device__ __forceinline__ float tanhf_f(float x) {
    float xc = fminf(fmaxf(x, -15.0f), 15.0f);
    float e = __expf(2.0f * xc);
    return __fdividef(e - 1.0f, e + 1.0f);
}

// ---------------- weight prep (split into 3 launches so gemm0 is ncu launch #5) ----
// Gate-column permutation: for unit u (0..127), gate g (i=0,f=1,g=2,o=3):
//   c(u,g) = (u>>2)*16 + (u&3)*2 + (g&1) + (g>>1)*8
__device__ __forceinline__ int perm_oc(int n) {
    int blk = n >> 4, w = n & 15;
    int ghi = w >> 3, pos = (w & 7) >> 1, glo = w & 1;
    int u = blk * 4 + pos;
    int g = ghi * 2 + glo;
    return g * 128 + u;
}
__global__ void ip_permW(const float* __restrict__ Wi, const float* __restrict__ Wh,
                         float* __restrict__ WT)
{
    int t = blockIdx.x * 256 + threadIdx.x;    // [0, 512*256)
    int n = t >> 8;
    int k = t & 255;
    int oc = perm_oc(n);
    float w = (k < 128) ? Wi[k * PG4 + oc] : Wh[(k - 128) * PG4 + oc];
    WT[t] = __uint_as_float(f2tf32(w));
}
__global__ void ip_permB(const float* __restrict__ b0, const float* __restrict__ b1)
{
    int n = blockIdx.x * 256 + threadIdx.x;    // [0, 512)
    int oc = perm_oc(n);
    g_bP0[n] = b0[oc];
    g_bP1[n] = b1[oc];
}

// ---------------- tf32 mma.sync GEMM + fused LSTM epilogue ----------------
// CTA: 128 rows x 128 gate-cols. 8 warps (4 M x 2 N), warp tile 32x64.
// K = 256 in 8 chunks of 32. Smem rows padded to 36 floats (conflict-free frags).
// 2 CTAs/SM target: ~124 regs, smem 73728 B.
#define A_STRIDE 36
#define A_BUF_BYTES (128 * A_STRIDE * 4)   // 18432
#define B_BUF_BYTES (128 * A_STRIDE * 4)   // 18432
#define SMEM_TOTAL_GEMM (2 * A_BUF_BYTES + 2 * B_BUF_BYTES)   // 73728

__global__ __launch_bounds__(256, 2) void ip_lstm_mma(
    const float* __restrict__ X, int xs,
    const float* __restrict__ Hp, int hs,
    const float* __restrict__ Cold,
    const float* __restrict__ WT, const float* __restrict__ bP,
    float* __restrict__ outC, float* __restrict__ outH)
{
    extern __shared__ char smem[];
    uint32_t* Ab[2] = { (uint32_t*)smem, (uint32_t*)(smem + A_BUF_BYTES) };
    uint32_t* Bb[2] = { (uint32_t*)(smem + 2 * A_BUF_BYTES),
                        (uint32_t*)(smem + 2 * A_BUF_BYTES + B_BUF_BYTES) };

    int tid = threadIdx.x;
    int wid = tid >> 5, lane = tid & 31;
    int wm = wid & 3, wn = wid >> 2;          // 4 M-warps x 2 N-warps
    int row0 = blockIdx.y * 128;
    int col0 = blockIdx.x * 128;

    float acc[2][8][4];
#pragma unroll
    for (int mt = 0; mt < 2; mt++)
#pragma unroll
        for (int nt = 0; nt < 8; nt++)
#pragma unroll
            for (int q = 0; q < 4; q++) acc[mt][nt][q] = 0.0f;

    // bias registers (permuted layout)
    float bI[4], bF[4], bG[4], bO[4];
#pragma unroll
    for (int p = 0; p < 4; p++) {
        int c0 = col0 + wn * 64 + p * 16 + (lane & 3) * 2;
        bI[p] = bP[c0];     bF[p] = bP[c0 + 1];
        bG[p] = bP[c0 + 8]; bO[p] = bP[c0 + 9];
    }

    // prologue: chunk 0
    {
        // B chunk 0: 128 n-rows x 32 k (4 float4 per thread) via cp.async
#pragma unroll
        for (int j = 0; j < 4; j++) {
            int fid = j * 256 + tid;           // [0,1024)
            int n = fid >> 3, q = fid & 7;
            uint32_t dst = smem_u32((char*)Bb[0] + n * (A_STRIDE * 4) + q * 16);
            CP_ASYNC16(dst, WT + (size_t)(col0 + n) * PK + q * 4);
        }
        CP_COMMIT();
        // A chunk 0: 128 rows x 32 k via LDG + cvt + STS
#pragma unroll
        for (int j = 0; j < 4; j++) {
            int fid = j * 256 + tid;
            int r = fid >> 3, q = fid & 7;
            float4 v = *(const float4*)(X + (size_t)(row0 + r) * xs + q * 4);
            uint4 u4 = make_uint4(f2tf32(v.x), f2tf32(v.y), f2tf32(v.z), f2tf32(v.w));
            *(uint4*)((char*)Ab[0] + r * (A_STRIDE * 4) + q * 16) = u4;
        }
        CP_WAIT0();
        __syncthreads();
    }

    int a_base = (wm * 32 + (lane >> 2)) * A_STRIDE;
    int b_base = (wn * 64 + (lane >> 2)) * A_STRIDE;
    int kc = lane & 3;

#pragma unroll 1
    for (int ch = 0; ch < 8; ch++) {
        int buf = ch & 1;
        float4 stage[4];
        if (ch < 7) {
            int chn = ch + 1;
            int ka = (chn & 3) * 32;   // A: k within current source (X or Hp)
            int kb = chn * 32;         // B: global k within combined WT (0..255)
#pragma unroll
            for (int j = 0; j < 4; j++) {
                int fid = j * 256 + tid;
                int n = fid >> 3, q = fid & 7;
                uint32_t dst = smem_u32((char*)Bb[buf ^ 1] + n * (A_STRIDE * 4) + q * 16);
                CP_ASYNC16(dst, WT + (size_t)(col0 + n) * PK + kb + q * 4);
            }
            CP_COMMIT();
            const float* Asrc = (chn < 4) ? X : Hp;
            int astr = (chn < 4) ? xs : hs;
#pragma unroll
            for (int j = 0; j < 4; j++) {
                int fid = j * 256 + tid;
                int r = fid >> 3, q = fid & 7;
                stage[j] = *(const float4*)(Asrc + (size_t)(row0 + r) * astr + ka + q * 4);
            }
        }

        uint32_t* Abuf = Ab[buf];
        uint32_t* Bbuf = Bb[buf];
#pragma unroll
        for (int ks = 0; ks < 4; ks++) {
            int kk = ks * 8 + kc;
            uint32_t a[2][4];
#pragma unroll
            for (int mt = 0; mt < 2; mt++) {
                int rb = a_base + mt * 16 * A_STRIDE;
                a[mt][0] = Abuf[rb + kk];
                a[mt][1] = Abuf[rb + 8 * A_STRIDE + kk];
                a[mt][2] = Abuf[rb + kk + 4];
                a[mt][3] = Abuf[rb + 8 * A_STRIDE + kk + 4];
            }
            uint32_t b[8][2];
#pragma unroll
            for (int nt = 0; nt < 8; nt++) {
                int nb = b_base + nt * 8 * A_STRIDE;
                b[nt][0] = Bbuf[nb + kk];
                b[nt][1] = Bbuf[nb + kk + 4];
            }
#pragma unroll
            for (int mt = 0; mt < 2; mt++)
#pragma unroll
                for (int nt = 0; nt < 8; nt++)
                    mma8(acc[mt][nt], a[mt], b[nt]);
        }

        if (ch < 7) {
#pragma unroll
            for (int j = 0; j < 4; j++) {
                int fid = j * 256 + tid;
                int r = fid >> 3, q = fid & 7;
                float4 v = stage[j];
                uint4 u4 = make_uint4(f2tf32(v.x), f2tf32(v.y), f2tf32(v.z), f2tf32(v.w));
                *(uint4*)((char*)Ab[buf ^ 1] + r * (A_STRIDE * 4) + q * 16) = u4;
            }
            CP_WAIT0();
        }
        __syncthreads();
    }

    // ---- fused LSTM epilogue (no shuffles; thread owns all 4 gates of its units) ----
#pragma unroll
    for (int mt = 0; mt < 2; mt++) {
        int r = row0 + wm * 32 + mt * 16 + (lane >> 2);
#pragma unroll
        for (int p = 0; p < 4; p++) {
            int u = (col0 >> 2) + wn * 16 + p * 4 + (lane & 3);
            float co0 = Cold[(size_t)r * PH + u];
            float co1 = Cold[(size_t)(r + 8) * PH + u];
            float iv = acc[mt][2 * p][0] + bI[p];
            float fv = acc[mt][2 * p][1] + bF[p];
            float gv = acc[mt][2 * p + 1][0] + bG[p];
            float ov = acc[mt][2 * p + 1][1] + bO[p];
            float cn0 = sigf(fv) * co0 + sigf(iv) * tanhf_f(gv);
            float hn0 = sigf(ov) * tanhf_f(cn0);
            float iv1 = acc[mt][2 * p][2] + bI[p];
            float fv1 = acc[mt][2 * p][3] + bF[p];
            float gv1 = acc[mt][2 * p + 1][2] + bG[p];
            float ov1 = acc[mt][2 * p + 1][3] + bO[p];
            float cn1 = sigf(fv1) * co1 + sigf(iv1) * tanhf_f(gv1);
            float hn1 = sigf(ov1) * tanhf_f(cn1);

            outC[(size_t)r * PG4 + u] = cn0;
            outH[(size_t)r * PG4 + u] = hn0;
            outC[(size_t)(r + 8) * PG4 + u] = cn1;
            outH[(size_t)(r + 8) * PG4 + u] = hn1;
        }
    }
}

// ---------------- mask exit/raise nodes: contrib <- old state ----------------
__global__ void ip_mask(const float* __restrict__ hc0, const float* __restrict__ hh0,
                        const float* __restrict__ hc1, const float* __restrict__ hh1,
                        const int* __restrict__ exi, const int* __restrict__ rai)
{
    int b = blockIdx.x;
    int node = blockIdx.y ? rai[b] : exi[b];
    int tid = threadIdx.x;  // 128
    size_t r = (size_t)b * PN + node;
    float* dst = g_contrib + r * PG4;
    size_t rb = r * PH;
    dst[tid]       = hc0[rb + tid];
    dst[128 + tid] = hh0[rb + tid];
    dst[256 + tid] = hc1[rb + tid];
    dst[384 + tid] = hh1[rb + tid];
}

// ---------------- FUSED decision heads + weighted scatter (one contrib pass) -----
__global__ __launch_bounds__(256) void ip_decagg(
    const float* __restrict__ Wr, const float* __restrict__ brs,
    const float* __restrict__ Wb, const float* __restrict__ bbs,
    const float* __restrict__ ipin,
    const int* __restrict__ ti, const int* __restrict__ fi, const int* __restrict__ ri,
    const int* __restrict__ exi, const int* __restrict__ rai,
    const int* __restrict__ slim, const int* __restrict__ cstep, int cs_fallback)
{
    __shared__ float sW[2048];  // [0:1024) W_raise, [1024:2048) W_branch
    int tid = threadIdx.x;
    for (int i = tid; i < 1024; i += 256) { sW[i] = Wr[i]; sW[1024 + i] = Wb[i]; }
    __syncthreads();

    int lane = tid & 31;
    int row = blockIdx.x * 8 + (tid >> 5);
    int b = row >> 11, n = row & 2047;

    // done batches contribute nothing the output reads — skip entirely
    int cs = cstep ? cstep[0] : cs_fallback;
    if (cs >= slim[b]) return;

    const float* crow = g_contrib + (size_t)row * PG4;
    float4 v[4];
#pragma unroll
    for (int t2 = 0; t2 < 4; t2++) v[t2] = *(const float4*)&crow[lane * 4 + t2 * 128];

    float r0 = 0.f, r1 = 0.f, q0 = 0.f, q1 = 0.f;
#pragma unroll
    for (int t2 = 0; t2 < 4; t2++) {
        int cb = lane * 4 + t2 * 128;
        float vv[4] = {v[t2].x, v[t2].y, v[t2].z, v[t2].w};
#pragma unroll
        for (int q = 0; q < 4; q++) {
            float w = vv[q];
            int c2 = (cb + q) * 2;
            r0 = fmaf(w, sW[c2 + 0], r0);
            r1 = fmaf(w, sW[c2 + 1], r1);
            q0 = fmaf(w, sW[1024 + c2 + 0], q0);
            q1 = fmaf(w, sW[1024 + c2 + 1], q1);
        }
    }
#pragma unroll
    for (int o = 16; o > 0; o >>= 1) {
        r0 += __shfl_xor_sync(0xffffffffu, r0, o);
        r1 += __shfl_xor_sync(0xffffffffu, r1, o);
        q0 += __shfl_xor_sync(0xffffffffu, q0, o);
        q1 += __shfl_xor_sync(0xffffffffu, q1, o);
    }

    float lr = (r0 + brs[0]) - (r1 + brs[1]);
    float p_raise = 1.0f / (1.0f + expf(-lr));
    float p_no = 1.0f - p_raise;
    if (n == exi[b] || n == rai[b]) { p_raise = 0.0f; p_no = 1.0f; }
    float lb = (q0 + bbs[0]) - (q1 + bbs[1]);
    float pb0 = 1.0f / (1.0f + expf(-lb));
    float pb1 = 1.0f - pb0;

    float ipv = ipin[row];
    float wr_ = p_raise * ipv;
    float wt_ = p_no * pb0 * ipv;
    float wf_ = p_no * pb1 * ipv;

    int tr = ri[row], tt = ti[row], tf = fi[row];
    if (lane == 0) {
        int bb2 = b << 11;
        atomicAdd(&g_ipnew[bb2 + tr], wr_);
        atomicAdd(&g_ipnew[bb2 + tt], wt_);
        atomicAdd(&g_ipnew[bb2 + tf], wf_);
    }

    size_t bb2 = (size_t)(b << 11);
    if (wr_ != 0.0f) {
        float* pr = g_accum + (bb2 + tr) * PG4 + lane * 4;
#pragma unroll
        for (int t2 = 0; t2 < 4; t2++)
            red4(pr + t2 * 128, v[t2].x * wr_, v[t2].y * wr_, v[t2].z * wr_, v[t2].w * wr_);
    }
    if (wt_ != 0.0f) {
        float* pr = g_accum + (bb2 + tt) * PG4 + lane * 4;
#pragma unroll
        for (int t2 = 0; t2 < 4; t2++)
            red4(pr + t2 * 128, v[t2].x * wt_, v[t2].y * wt_, v[t2].z * wt_, v[t2].w * wt_);
    }
    if (wf_ != 0.0f) {
        float* pr = g_accum + (bb2 + tf) * PG4 + lane * 4;
#pragma unroll
        for (int t2 = 0; t2 < 4; t2++)
            red4(pr + t2 * 128, v[t2].x * wf_, v[t2].y * wf_, v[t2].z * wf_, v[t2].w * wf_);
    }
}

// ---------------- finalize: divide, not_done gate, pack output ----------------
__global__ void ip_finalize(
    const float* __restrict__ hc0, const float* __restrict__ hh0,
    const float* __restrict__ hc1, const float* __restrict__ hh1,
    const float* __restrict__ ipold, const int* __restrict__ slim,
    const int* __restrict__ cstep, int cs_fallback, float* __restrict__ out)
{
    int row = blockIdx.x;
    int tid = threadIdx.x;  // 128
    int b = row >> 11;
    int cs = cstep ? cstep[0] : cs_fallback;
    bool nd = cs < slim[b];
    size_t ob = (size_t)row * 513;
    if (nd) {
        float ipn = g_ipnew[row];
        float inv = 1.0f / (ipn + 1e-7f);
        const float* arow = g_accum + (size_t)row * PG4;
        out[ob + tid]       = arow[tid] * inv;
        out[ob + 128 + tid] = arow[128 + tid] * inv;
        out[ob + 256 + tid] = arow[256 + tid] * inv;
        out[ob + 384 + tid] = arow[384 + tid] * inv;
        if (tid == 0) out[ob + 512] = ipn;
    } else {
        size_t rb = (size_t)row * PH;
        out[ob + tid]       = hc0[rb + tid];
        out[ob + 128 + tid] = hh0[rb + tid];
        out[ob + 256 + tid] = hc1[rb + tid];
        out[ob + 384 + tid] = hh1[rb + tid];
        if (tid == 0) out[ob + 512] = ipold[row];
    }
}

// ---------------- host launcher ----------------
extern "C" void kernel_launch(void* const* d_in, const int* in_sizes, int n_in,
                              void* d_out, int out_size)
{
    const float* emb  = (const float*)d_in[0];
    const float* hc0  = (const float*)d_in[1];
    const float* hh0  = (const float*)d_in[2];
    const float* hc1  = (const float*)d_in[3];
    const float* hh1  = (const float*)d_in[4];
    const float* ip   = (const float*)d_in[5];
    const float* Wi0  = (const float*)d_in[6];
    const float* Wh0  = (const float*)d_in[7];
    const float* b0   = (const float*)d_in[8];
    const float* Wi1  = (const float*)d_in[9];
    const float* Wh1  = (const float*)d_in[10];
    const float* b1   = (const float*)d_in[11];
    const float* Wr   = (const float*)d_in[12];
    const float* br   = (const float*)d_in[13];
    const float* Wb   = (const float*)d_in[14];
    const float* bb   = (const float*)d_in[15];
    const int* ti     = (const int*)d_in[16];
    const int* fi     = (const int*)d_in[17];
    const int* ri     = (const int*)d_in[18];
    const int* exi    = (const int*)d_in[19];
    const int* rai    = (const int*)d_in[20];
    const int* slim   = (const int*)d_in[21];
    const int* cstep  = (n_in >= 23) ? (const int*)d_in[22] : nullptr;
    float* out = (float*)d_out;

    float *contrib, *accum, *ipnew, *WT0, *WT1, *bP0, *bP1;
    cudaGetSymbolAddress((void**)&contrib, g_contrib);
    cudaGetSymbolAddress((void**)&accum,   g_accum);
    cudaGetSymbolAddress((void**)&ipnew,   g_ipnew);
    cudaGetSymbolAddress((void**)&WT0,     g_WT0);
    cudaGetSymbolAddress((void**)&WT1,     g_WT1);
    cudaGetSymbolAddress((void**)&bP0,     g_bP0);
    cudaGetSymbolAddress((void**)&bP1,     g_bP1);

    cudaFuncSetAttribute(ip_lstm_mma,
                         cudaFuncAttributeMaxDynamicSharedMemorySize, SMEM_TOTAL_GEMM);

    // launches 0-4 (so ncu -s 5 -c 1 lands on gemm0)
    cudaMemsetAsync(accum, 0, sizeof(float) * (size_t)PM * PG4, 0);   // 0
    cudaMemsetAsync(ipnew, 0, sizeof(float) * (size_t)PM, 0);         // 1
    ip_permW<<<512, 256>>>(Wi0, Wh0, WT0);                            // 2
    ip_permW<<<512, 256>>>(Wi1, Wh1, WT1);                            // 3
    ip_permB<<<2, 256>>>(b0, b1);                                     // 4

    dim3 ggrid(4, PM / 128);
    // Layer 0 (launch 5: ncu target): x = emb, h = hh0, c = hc0
    ip_lstm_mma<<<ggrid, 256, SMEM_TOTAL_GEMM>>>(
        emb, PH, hh0, PH, hc0, WT0, bP0, contrib + 0, contrib + 128);
    // Layer 1: x = h0n (stride 512), h = hh1, c = hc1
    ip_lstm_mma<<<ggrid, 256, SMEM_TOTAL_GEMM>>>(
        contrib + 128, PG4, hh1, PH, hc1, WT1, bP1, contrib + 256, contrib + 384);

    ip_mask<<<dim3(PB, 2), 128>>>(hc0, hh0, hc1, hh1, exi, rai);

    ip_decagg<<<PM / 8, 256>>>(Wr, br, Wb, bb, ip, ti, fi, ri, exi, rai,
                               slim, cstep, 5);

    ip_finalize<<<PM, 128>>>(hc0, hh0, hc1, hh1, ip, slim, cstep, 5, out);
}

// round 8
// speedup vs baseline: 2.7294x; 1.0552x over previous
#include <cuda_runtime.h>
#include <math.h>
#include <stdint.h>

// Problem constants
#define PB 32
#define PN 2048
#define PH 128
#define PG4 512
#define PM (PB * PN)   // 65536 rows
#define PK 256         // combined K = [X | H]

// ---------------- device scratch (no allocations allowed) ----------------
__device__ float g_contrib[(size_t)PM * PG4];   // [c0 | h0 | c1 | h1] per row
__device__ float g_WT0[PG4 * PK];               // B operand, layer0: [n][k], tf32-rounded
__device__ float g_WT1[PG4 * PK];               // layer1
__device__ float g_bP0[PG4];
__device__ float g_bP1[PG4];
__device__ float g_ipnew[PM];
__device__ int   g_cnt[PM];                     // incoming-edge counts per target
__device__ int   g_off[PM];                     // CSR offsets
__device__ int   g_cur[PM];                     // fill cursors (post-fill: off + filled)
__device__ int   g_esrc[3 * PM];                // edge source rows
__device__ float g_ew[3 * PM];                  // edge weights

// ---------------- helpers ----------------
__device__ __forceinline__ uint32_t smem_u32(const void* p) {
    uint32_t a;
    asm("{ .reg .u64 t; cvta.to.shared.u64 t, %1; cvt.u32.u64 %0, t; }" : "=r"(a) : "l"(p));
    return a;
}
__device__ __forceinline__ uint32_t f2tf32(float x) {
    uint32_t r;
    asm("cvt.rna.tf32.f32 %0, %1;" : "=r"(r) : "f"(x));
    return r;
}
__device__ __forceinline__ void mma8(float* d, const uint32_t* a, const uint32_t* b) {
    asm volatile(
        "mma.sync.aligned.m16n8k8.row.col.f32.tf32.tf32.f32 "
        "{%0,%1,%2,%3}, {%4,%5,%6,%7}, {%8,%9}, {%0,%1,%2,%3};"
        : "+f"(d[0]), "+f"(d[1]), "+f"(d[2]), "+f"(d[3])
        : "r"(a[0]), "r"(a[1]), "r"(a[2]), "r"(a[3]), "r"(b[0]), "r"(b[1]));
}
#define CP_ASYNC16(s, g) asm volatile("cp.async.cg.shared.global [%0], [%1], 16;" :: "r"(s), "l"(g))
#define CP_COMMIT() asm volatile("cp.async.commit_group;" ::: "memory")
#define CP_WAIT0() asm volatile("cp.async.wait_group 0;" ::: "memory")

__device__ __forceinline__ float sigf(float x) {
    return __fdividef(1.0f, 1.0f + __expf(-x));
}
__device__ __forceinline__ float tanhf_f(float x) {
    float xc = fminf(fmaxf(x, -15.0f), 15.0f);
    float e = __expf(2.0f * xc);
    return __fdividef(e - 1.0f, e + 1.0f);
}

// ---------------- weight prep ----------------
// Gate-column permutation: for unit u (0..127), gate g (i=0,f=1,g=2,o=3):
//   c(u,g) = (u>>2)*16 + (u&3)*2 + (g&1) + (g>>1)*8
__device__ __forceinline__ int perm_oc(int n) {
    int blk = n >> 4, w = n & 15;
    int ghi = w >> 3, pos = (w & 7) >> 1, glo = w & 1;
    int u = blk * 4 + pos;
    int g = ghi * 2 + glo;
    return g * 128 + u;
}
__global__ void ip_permW(const float* __restrict__ Wi, const float* __restrict__ Wh,
                         float* __restrict__ WT)
{
    int t = blockIdx.x * 256 + threadIdx.x;    // [0, 512*256)
    int n = t >> 8;
    int k = t & 255;
    int oc = perm_oc(n);
    float w = (k < 128) ? Wi[k * PG4 + oc] : Wh[(k - 128) * PG4 + oc];
    WT[t] = __uint_as_float(f2tf32(w));
}
__global__ void ip_permB(const float* __restrict__ b0, const float* __restrict__ b1)
{
    int n = blockIdx.x * 256 + threadIdx.x;    // [0, 512)
    int oc = perm_oc(n);
    g_bP0[n] = b0[oc];
    g_bP1[n] = b1[oc];
}

// ---------------- CSR: count incoming edges per target --------------------
__global__ void ip_count(const int* __restrict__ ti, const int* __restrict__ fi,
                         const int* __restrict__ ri)
{
    int s = blockIdx.x * 256 + threadIdx.x;
    int bb = (s >> 11) << 11;
    atomicAdd(&g_cnt[bb + ri[s]], 1);
    atomicAdd(&g_cnt[bb + ti[s]], 1);
    atomicAdd(&g_cnt[bb + fi[s]], 1);
}

// ---------------- CSR: per-batch exclusive scan of counts; zero ipnew ------
__global__ __launch_bounds__(512) void ip_scan()
{
    __shared__ int part[512];
    int b = blockIdx.x;          // 32 batches
    int t = threadIdx.x;         // 512
    int base = b << 11;

    int c0 = g_cnt[base + 4 * t + 0];
    int c1 = g_cnt[base + 4 * t + 1];
    int c2 = g_cnt[base + 4 * t + 2];
    int c3 = g_cnt[base + 4 * t + 3];
    int l0 = c0, l1 = l0 + c1, l2 = l1 + c2, l3 = l2 + c3;
    part[t] = l3;
    __syncthreads();
    for (int o = 1; o < 512; o <<= 1) {
        int v = (t >= o) ? part[t - o] : 0;
        __syncthreads();
        part[t] += v;
        __syncthreads();
    }
    int ex = (t == 0) ? 0 : part[t - 1];
    int gb = b * 6144 + ex;
    g_off[base + 4 * t + 0] = gb;
    g_off[base + 4 * t + 1] = gb + l0;
    g_off[base + 4 * t + 2] = gb + l1;
    g_off[base + 4 * t + 3] = gb + l2;
    g_cur[base + 4 * t + 0] = gb;
    g_cur[base + 4 * t + 1] = gb + l0;
    g_cur[base + 4 * t + 2] = gb + l1;
    g_cur[base + 4 * t + 3] = gb + l2;
    g_ipnew[base + 4 * t + 0] = 0.0f;
    g_ipnew[base + 4 * t + 1] = 0.0f;
    g_ipnew[base + 4 * t + 2] = 0.0f;
    g_ipnew[base + 4 * t + 3] = 0.0f;
}

// ---------------- tf32 mma.sync GEMM + fused LSTM epilogue ----------------
// CTA: 128 rows x 128 gate-cols. 8 warps (4 M x 2 N), warp tile 32x64.
// K = 256 in 8 chunks of 32. Smem rows padded to 36 floats (conflict-free frags).
#define A_STRIDE 36
#define A_BUF_BYTES (128 * A_STRIDE * 4)   // 18432
#define B_BUF_BYTES (128 * A_STRIDE * 4)   // 18432
#define SMEM_TOTAL_GEMM (2 * A_BUF_BYTES + 2 * B_BUF_BYTES)   // 73728

__global__ __launch_bounds__(256, 2) void ip_lstm_mma(
    const float* __restrict__ X, int xs,
    const float* __restrict__ Hp, int hs,
    const float* __restrict__ Cold,
    const float* __restrict__ WT, const float* __restrict__ bP,
    float* __restrict__ outC, float* __restrict__ outH)
{
    extern __shared__ char smem[];
    uint32_t* Ab[2] = { (uint32_t*)smem, (uint32_t*)(smem + A_BUF_BYTES) };
    uint32_t* Bb[2] = { (uint32_t*)(smem + 2 * A_BUF_BYTES),
                        (uint32_t*)(smem + 2 * A_BUF_BYTES + B_BUF_BYTES) };

    int tid = threadIdx.x;
    int wid = tid >> 5, lane = tid & 31;
    int wm = wid & 3, wn = wid >> 2;          // 4 M-warps x 2 N-warps
    int row0 = blockIdx.y * 128;
    int col0 = blockIdx.x * 128;

    float acc[2][8][4];
#pragma unroll
    for (int mt = 0; mt < 2; mt++)
#pragma unroll
        for (int nt = 0; nt < 8; nt++)
#pragma unroll
            for (int q = 0; q < 4; q++) acc[mt][nt][q] = 0.0f;

    float bI[4], bF[4], bG[4], bO[4];
#pragma unroll
    for (int p = 0; p < 4; p++) {
        int c0 = col0 + wn * 64 + p * 16 + (lane & 3) * 2;
        bI[p] = bP[c0];     bF[p] = bP[c0 + 1];
        bG[p] = bP[c0 + 8]; bO[p] = bP[c0 + 9];
    }

    // prologue: chunk 0
    {
#pragma unroll
        for (int j = 0; j < 4; j++) {
            int fid = j * 256 + tid;
            int n = fid >> 3, q = fid & 7;
            uint32_t dst = smem_u32((char*)Bb[0] + n * (A_STRIDE * 4) + q * 16);
            CP_ASYNC16(dst, WT + (size_t)(col0 + n) * PK + q * 4);
        }
        CP_COMMIT();
#pragma unroll
        for (int j = 0; j < 4; j++) {
            int fid = j * 256 + tid;
            int r = fid >> 3, q = fid & 7;
            float4 v = *(const float4*)(X + (size_t)(row0 + r) * xs + q * 4);
            uint4 u4 = make_uint4(f2tf32(v.x), f2tf32(v.y), f2tf32(v.z), f2tf32(v.w));
            *(uint4*)((char*)Ab[0] + r * (A_STRIDE * 4) + q * 16) = u4;
        }
        CP_WAIT0();
        __syncthreads();
    }

    int a_base = (wm * 32 + (lane >> 2)) * A_STRIDE;
    int b_base = (wn * 64 + (lane >> 2)) * A_STRIDE;
    int kc = lane & 3;

#pragma unroll 1
    for (int ch = 0; ch < 8; ch++) {
        int buf = ch & 1;
        float4 stage[4];
        if (ch < 7) {
            int chn = ch + 1;
            int ka = (chn & 3) * 32;   // A: k within current source (X or Hp)
            int kb = chn * 32;         // B: global k within combined WT (0..255)
#pragma unroll
            for (int j = 0; j < 4; j++) {
                int fid = j * 256 + tid;
                int n = fid >> 3, q = fid & 7;
                uint32_t dst = smem_u32((char*)Bb[buf ^ 1] + n * (A_STRIDE * 4) + q * 16);
                CP_ASYNC16(dst, WT + (size_t)(col0 + n) * PK + kb + q * 4);
            }
            CP_COMMIT();
            const float* Asrc = (chn < 4) ? X : Hp;
            int astr = (chn < 4) ? xs : hs;
#pragma unroll
            for (int j = 0; j < 4; j++) {
                int fid = j * 256 + tid;
                int r = fid >> 3, q = fid & 7;
                stage[j] = *(const float4*)(Asrc + (size_t)(row0 + r) * astr + ka + q * 4);
            }
        }

        uint32_t* Abuf = Ab[buf];
        uint32_t* Bbuf = Bb[buf];
#pragma unroll
        for (int ks = 0; ks < 4; ks++) {
            int kk = ks * 8 + kc;
            uint32_t a[2][4];
#pragma unroll
            for (int mt = 0; mt < 2; mt++) {
                int rb = a_base + mt * 16 * A_STRIDE;
                a[mt][0] = Abuf[rb + kk];
                a[mt][1] = Abuf[rb + 8 * A_STRIDE + kk];
                a[mt][2] = Abuf[rb + kk + 4];
                a[mt][3] = Abuf[rb + 8 * A_STRIDE + kk + 4];
            }
            uint32_t b[8][2];
#pragma unroll
            for (int nt = 0; nt < 8; nt++) {
                int nb = b_base + nt * 8 * A_STRIDE;
                b[nt][0] = Bbuf[nb + kk];
                b[nt][1] = Bbuf[nb + kk + 4];
            }
#pragma unroll
            for (int mt = 0; mt < 2; mt++)
#pragma unroll
                for (int nt = 0; nt < 8; nt++)
                    mma8(acc[mt][nt], a[mt], b[nt]);
        }

        if (ch < 7) {
#pragma unroll
            for (int j = 0; j < 4; j++) {
                int fid = j * 256 + tid;
                int r = fid >> 3, q = fid & 7;
                float4 v = stage[j];
                uint4 u4 = make_uint4(f2tf32(v.x), f2tf32(v.y), f2tf32(v.z), f2tf32(v.w));
                *(uint4*)((char*)Ab[buf ^ 1] + r * (A_STRIDE * 4) + q * 16) = u4;
            }
            CP_WAIT0();
        }
        __syncthreads();
    }

    // ---- fused LSTM epilogue ----
#pragma unroll
    for (int mt = 0; mt < 2; mt++) {
        int r = row0 + wm * 32 + mt * 16 + (lane >> 2);
#pragma unroll
        for (int p = 0; p < 4; p++) {
            int u = (col0 >> 2) + wn * 16 + p * 4 + (lane & 3);
            float co0 = Cold[(size_t)r * PH + u];
            float co1 = Cold[(size_t)(r + 8) * PH + u];
            float iv = acc[mt][2 * p][0] + bI[p];
            float fv = acc[mt][2 * p][1] + bF[p];
            float gv = acc[mt][2 * p + 1][0] + bG[p];
            float ov = acc[mt][2 * p + 1][1] + bO[p];
            float cn0 = sigf(fv) * co0 + sigf(iv) * tanhf_f(gv);
            float hn0 = sigf(ov) * tanhf_f(cn0);
            float iv1 = acc[mt][2 * p][2] + bI[p];
            float fv1 = acc[mt][2 * p][3] + bF[p];
            float gv1 = acc[mt][2 * p + 1][2] + bG[p];
            float ov1 = acc[mt][2 * p + 1][3] + bO[p];
            float cn1 = sigf(fv1) * co1 + sigf(iv1) * tanhf_f(gv1);
            float hn1 = sigf(ov1) * tanhf_f(cn1);

            outC[(size_t)r * PG4 + u] = cn0;
            outH[(size_t)r * PG4 + u] = hn0;
            outC[(size_t)(r + 8) * PG4 + u] = cn1;
            outH[(size_t)(r + 8) * PG4 + u] = hn1;
        }
    }
}

// ---------------- mask exit/raise nodes: contrib <- old state ----------------
__global__ void ip_mask(const float* __restrict__ hc0, const float* __restrict__ hh0,
                        const float* __restrict__ hc1, const float* __restrict__ hh1,
                        const int* __restrict__ exi, const int* __restrict__ rai)
{
    int b = blockIdx.x;
    int node = blockIdx.y ? rai[b] : exi[b];
    int tid = threadIdx.x;  // 128
    size_t r = (size_t)b * PN + node;
    float* dst = g_contrib + r * PG4;
    size_t rb = r * PH;
    dst[tid]       = hc0[rb + tid];
    dst[128 + tid] = hh0[rb + tid];
    dst[256 + tid] = hc1[rb + tid];
    dst[384 + tid] = hh1[rb + tid];
}

// ---------------- decision heads + CSR edge fill + ip scatter ----------------
__global__ __launch_bounds__(256) void ip_decision(
    const float* __restrict__ Wr, const float* __restrict__ brs,
    const float* __restrict__ Wb, const float* __restrict__ bbs,
    const float* __restrict__ ipin,
    const int* __restrict__ ti, const int* __restrict__ fi, const int* __restrict__ ri,
    const int* __restrict__ exi, const int* __restrict__ rai,
    const int* __restrict__ slim, const int* __restrict__ cstep, int cs_fallback)
{
    __shared__ float sW[2048];  // [0:1024) W_raise, [1024:2048) W_branch
    int tid = threadIdx.x;
    for (int i = tid; i < 1024; i += 256) { sW[i] = Wr[i]; sW[1024 + i] = Wb[i]; }
    __syncthreads();

    int lane = tid & 31;
    int row = blockIdx.x * 8 + (tid >> 5);
    int b = row >> 11, n = row & 2047;

    // done batches: their outputs use old state; edges never read
    int cs = cstep ? cstep[0] : cs_fallback;
    if (cs >= slim[b]) return;

    const float* crow = g_contrib + (size_t)row * PG4;
    float4 v[4];
#pragma unroll
    for (int t2 = 0; t2 < 4; t2++) v[t2] = *(const float4*)&crow[lane * 4 + t2 * 128];

    float r0 = 0.f, r1 = 0.f, q0 = 0.f, q1 = 0.f;
#pragma unroll
    for (int t2 = 0; t2 < 4; t2++) {
        int cb = lane * 4 + t2 * 128;
        float vv[4] = {v[t2].x, v[t2].y, v[t2].z, v[t2].w};
#pragma unroll
        for (int q = 0; q < 4; q++) {
            float w = vv[q];
            int c2 = (cb + q) * 2;
            r0 = fmaf(w, sW[c2 + 0], r0);
            r1 = fmaf(w, sW[c2 + 1], r1);
            q0 = fmaf(w, sW[1024 + c2 + 0], q0);
            q1 = fmaf(w, sW[1024 + c2 + 1], q1);
        }
    }
#pragma unroll
    for (int o = 16; o > 0; o >>= 1) {
        r0 += __shfl_xor_sync(0xffffffffu, r0, o);
        r1 += __shfl_xor_sync(0xffffffffu, r1, o);
        q0 += __shfl_xor_sync(0xffffffffu, q0, o);
        q1 += __shfl_xor_sync(0xffffffffu, q1, o);
    }

    float lr = (r0 + brs[0]) - (r1 + brs[1]);
    float p_raise = 1.0f / (1.0f + expf(-lr));
    float p_no = 1.0f - p_raise;
    if (n == exi[b] || n == rai[b]) { p_raise = 0.0f; p_no = 1.0f; }
    float lb = (q0 + bbs[0]) - (q1 + bbs[1]);
    float pb0 = 1.0f / (1.0f + expf(-lb));
    float pb1 = 1.0f - pb0;

    float ipv = ipin[row];
    float wr_ = p_raise * ipv;
    float wt_ = p_no * pb0 * ipv;
    float wf_ = p_no * pb1 * ipv;

    if (lane == 0) {
        int bb2 = b << 11;
        int tr = bb2 + ri[row], tt = bb2 + ti[row], tf = bb2 + fi[row];
        atomicAdd(&g_ipnew[tr], wr_);
        atomicAdd(&g_ipnew[tt], wt_);
        atomicAdd(&g_ipnew[tf], wf_);
        if (wr_ != 0.0f) {
            int s = atomicAdd(&g_cur[tr], 1);
            g_esrc[s] = row; g_ew[s] = wr_;
        }
        if (wt_ != 0.0f) {
            int s = atomicAdd(&g_cur[tt], 1);
            g_esrc[s] = row; g_ew[s] = wt_;
        }
        if (wf_ != 0.0f) {
            int s = atomicAdd(&g_cur[tf], 1);
            g_esrc[s] = row; g_ew[s] = wf_;
        }
    }
}

// ---------------- gather + finalize: one pass, no atomics, no accum ----------
__global__ __launch_bounds__(128) void ip_gather(
    const float* __restrict__ hc0, const float* __restrict__ hh0,
    const float* __restrict__ hc1, const float* __restrict__ hh1,
    const float* __restrict__ ipold, const int* __restrict__ slim,
    const int* __restrict__ cstep, int cs_fallback, float* __restrict__ out)
{
    int row = blockIdx.x;
    int tid = threadIdx.x;  // 128
    int b = row >> 11;
    int cs = cstep ? cstep[0] : cs_fallback;
    bool nd = cs < slim[b];
    size_t ob = (size_t)row * 513;
    if (nd) {
        int s = g_off[row], e = g_cur[row];
        const float4* cb = (const float4*)g_contrib;
        float ax = 0.f, ay = 0.f, az = 0.f, aw = 0.f;
        for (int i = s; i < e; i++) {
            float w = g_ew[i];
            int src = g_esrc[i];
            float4 v = cb[(size_t)src * 128 + tid];
            ax = fmaf(w, v.x, ax); ay = fmaf(w, v.y, ay);
            az = fmaf(w, v.z, az); aw = fmaf(w, v.w, aw);
        }
        float ipn = g_ipnew[row];
        float inv = __fdividef(1.0f, ipn + 1e-7f);
        out[ob + 4 * tid + 0] = ax * inv;
        out[ob + 4 * tid + 1] = ay * inv;
        out[ob + 4 * tid + 2] = az * inv;
        out[ob + 4 * tid + 3] = aw * inv;
        if (tid == 0) out[ob + 512] = ipn;
    } else {
        size_t rb = (size_t)row * PH;
        out[ob + tid]       = hc0[rb + tid];
        out[ob + 128 + tid] = hh0[rb + tid];
        out[ob + 256 + tid] = hc1[rb + tid];
        out[ob + 384 + tid] = hh1[rb + tid];
        if (tid == 0) out[ob + 512] = ipold[row];
    }
}

// ---------------- host launcher ----------------
extern "C" void kernel_launch(void* const* d_in, const int* in_sizes, int n_in,
                              void* d_out, int out_size)
{
    const float* emb  = (const float*)d_in[0];
    const float* hc0  = (const float*)d_in[1];
    const float* hh0  = (const float*)d_in[2];
    const float* hc1  = (const float*)d_in[3];
    const float* hh1  = (const float*)d_in[4];
    const float* ip   = (const float*)d_in[5];
    const float* Wi0  = (const float*)d_in[6];
    const float* Wh0  = (const float*)d_in[7];
    const float* b0   = (const float*)d_in[8];
    const float* Wi1  = (const float*)d_in[9];
    const float* Wh1  = (const float*)d_in[10];
    const float* b1   = (const float*)d_in[11];
    const float* Wr   = (const float*)d_in[12];
    const float* br   = (const float*)d_in[13];
    const float* Wb   = (const float*)d_in[14];
    const float* bb   = (const float*)d_in[15];
    const int* ti     = (const int*)d_in[16];
    const int* fi     = (const int*)d_in[17];
    const int* ri     = (const int*)d_in[18];
    const int* exi    = (const int*)d_in[19];
    const int* rai    = (const int*)d_in[20];
    const int* slim   = (const int*)d_in[21];
    const int* cstep  = (n_in >= 23) ? (const int*)d_in[22] : nullptr;
    float* out = (float*)d_out;

    float *contrib, *WT0, *WT1;
    int* cnt;
    cudaGetSymbolAddress((void**)&contrib, g_contrib);
    cudaGetSymbolAddress((void**)&WT0,     g_WT0);
    cudaGetSymbolAddress((void**)&WT1,     g_WT1);
    cudaGetSymbolAddress((void**)&cnt,     g_cnt);

    cudaFuncSetAttribute(ip_lstm_mma,
                         cudaFuncAttributeMaxDynamicSharedMemorySize, SMEM_TOTAL_GEMM);

    // launch order chosen so ncu -s 5 -c 1 lands on gemm0
    cudaMemsetAsync(cnt, 0, sizeof(int) * (size_t)PM, 0);             // 0
    ip_count<<<PM / 256, 256>>>(ti, fi, ri);                          // 1
    ip_permW<<<512, 256>>>(Wi0, Wh0, WT0);                            // 2
    ip_permW<<<512, 256>>>(Wi1, Wh1, WT1);                            // 3
    ip_permB<<<2, 256>>>(b0, b1);                                     // 4

    dim3 ggrid(4, PM / 128);
    // Layer 0 (launch 5: ncu target)
    ip_lstm_mma<<<ggrid, 256, SMEM_TOTAL_GEMM>>>(
        emb, PH, hh0, PH, hc0, WT0, g_bP0, contrib + 0, contrib + 128);
    // Layer 1
    ip_lstm_mma<<<ggrid, 256, SMEM_TOTAL_GEMM>>>(
        contrib + 128, PG4, hh1, PH, hc1, WT1, g_bP1, contrib + 256, contrib + 384);

    ip_scan<<<PB, 512>>>();                                           // offsets + cursors + ipnew=0

    ip_mask<<<dim3(PB, 2), 128>>>(hc0, hh0, hc1, hh1, exi, rai);

    ip_decision<<<PM / 8, 256>>>(Wr, br, Wb, bb, ip, ti, fi, ri, exi, rai,
                                 slim, cstep, 5);

    ip_gather<<<PM, 128>>>(hc0, hh0, hc1, hh1, ip, slim, cstep, 5, out);
}

// round 9
// speedup vs baseline: 3.1047x; 1.1375x over previous
#include <cuda_runtime.h>
#include <math.h>
#include <stdint.h>

// Problem constants
#define PB 32
#define PN 2048
#define PH 128
#define PG4 512
#define PM (PB * PN)   // 65536 rows
#define PK 256         // combined K = [X | H]

// ---------------- device scratch (no allocations allowed) ----------------
__device__ float g_contrib[(size_t)PM * PG4];   // [c0 | h0 | c1 | h1] per row
__device__ float g_WT0[PG4 * PK];               // B operand, layer0: [n][k], tf32-rounded
__device__ float g_WT1[PG4 * PK];               // layer1
__device__ float g_bP0[PG4];
__device__ float g_bP1[PG4];
__device__ float g_ipnew[PM];
__device__ int   g_cnt[PM];                     // incoming-edge counts per target
__device__ int   g_off[PM];                     // CSR offsets
__device__ int   g_cur[PM];                     // fill cursors (post-fill: off + filled)
__device__ int   g_esrc[3 * PM];                // edge source rows
__device__ float g_ew[3 * PM];                  // edge weights

// ---------------- helpers ----------------
__device__ __forceinline__ uint32_t smem_u32(const void* p) {
    uint32_t a;
    asm("{ .reg .u64 t; cvta.to.shared.u64 t, %1; cvt.u32.u64 %0, t; }" : "=r"(a) : "l"(p));
    return a;
}
__device__ __forceinline__ uint32_t f2tf32(float x) {
    uint32_t r;
    asm("cvt.rna.tf32.f32 %0, %1;" : "=r"(r) : "f"(x));
    return r;
}
__device__ __forceinline__ void mma8(float* d, const uint32_t* a, const uint32_t* b) {
    asm volatile(
        "mma.sync.aligned.m16n8k8.row.col.f32.tf32.tf32.f32 "
        "{%0,%1,%2,%3}, {%4,%5,%6,%7}, {%8,%9}, {%0,%1,%2,%3};"
        : "+f"(d[0]), "+f"(d[1]), "+f"(d[2]), "+f"(d[3])
        : "r"(a[0]), "r"(a[1]), "r"(a[2]), "r"(a[3]), "r"(b[0]), "r"(b[1]));
}
#define CP_ASYNC16(s, g) asm volatile("cp.async.cg.shared.global [%0], [%1], 16;" :: "r"(s), "l"(g))
#define CP_COMMIT() asm volatile("cp.async.commit_group;" ::: "memory")
#define CP_WAIT0() asm volatile("cp.async.wait_group 0;" ::: "memory")
#define CP_WAIT1() asm volatile("cp.async.wait_group 1;" ::: "memory")

__device__ __forceinline__ float sigf(float x) {
    return __fdividef(1.0f, 1.0f + __expf(-x));
}
__device__ __forceinline__ float tanhf_f(float x) {
    float xc = fminf(fmaxf(x, -15.0f), 15.0f);
    float e = __expf(2.0f * xc);
    return __fdividef(e - 1.0f, e + 1.0f);
}

// ---------------- weight prep ----------------
// Gate-column permutation: for unit u (0..127), gate g (i=0,f=1,g=2,o=3):
//   c(u,g) = (u>>2)*16 + (u&3)*2 + (g&1) + (g>>1)*8
__device__ __forceinline__ int perm_oc(int n) {
    int blk = n >> 4, w = n & 15;
    int ghi = w >> 3, pos = (w & 7) >> 1, glo = w & 1;
    int u = blk * 4 + pos;
    int g = ghi * 2 + glo;
    return g * 128 + u;
}
__global__ void ip_permW(const float* __restrict__ Wi, const float* __restrict__ Wh,
                         float* __restrict__ WT)
{
    int t = blockIdx.x * 256 + threadIdx.x;    // [0, 512*256)
    int n = t >> 8;
    int k = t & 255;
    int oc = perm_oc(n);
    float w = (k < 128) ? Wi[k * PG4 + oc] : Wh[(k - 128) * PG4 + oc];
    WT[t] = __uint_as_float(f2tf32(w));
}
__global__ void ip_permB(const float* __restrict__ b0, const float* __restrict__ b1)
{
    int n = blockIdx.x * 256 + threadIdx.x;    // [0, 512)
    int oc = perm_oc(n);
    g_bP0[n] = b0[oc];
    g_bP1[n] = b1[oc];
}

// ---------------- CSR: count incoming edges per target --------------------
__global__ void ip_count(const int* __restrict__ ti, const int* __restrict__ fi,
                         const int* __restrict__ ri)
{
    int s = blockIdx.x * 256 + threadIdx.x;
    int bb = (s >> 11) << 11;
    atomicAdd(&g_cnt[bb + ri[s]], 1);
    atomicAdd(&g_cnt[bb + ti[s]], 1);
    atomicAdd(&g_cnt[bb + fi[s]], 1);
}

// ---------------- CSR: per-batch exclusive scan of counts; zero ipnew ------
__global__ __launch_bounds__(512) void ip_scan()
{
    __shared__ int part[512];
    int b = blockIdx.x;          // 32 batches
    int t = threadIdx.x;         // 512
    int base = b << 11;

    int c0 = g_cnt[base + 4 * t + 0];
    int c1 = g_cnt[base + 4 * t + 1];
    int c2 = g_cnt[base + 4 * t + 2];
    int c3 = g_cnt[base + 4 * t + 3];
    int l0 = c0, l1 = l0 + c1, l2 = l1 + c2, l3 = l2 + c3;
    part[t] = l3;
    __syncthreads();
    for (int o = 1; o < 512; o <<= 1) {
        int v = (t >= o) ? part[t - o] : 0;
        __syncthreads();
        part[t] += v;
        __syncthreads();
    }
    int ex = (t == 0) ? 0 : part[t - 1];
    int gb = b * 6144 + ex;
    g_off[base + 4 * t + 0] = gb;
    g_off[base + 4 * t + 1] = gb + l0;
    g_off[base + 4 * t + 2] = gb + l1;
    g_off[base + 4 * t + 3] = gb + l2;
    g_cur[base + 4 * t + 0] = gb;
    g_cur[base + 4 * t + 1] = gb + l0;
    g_cur[base + 4 * t + 2] = gb + l1;
    g_cur[base + 4 * t + 3] = gb + l2;
    g_ipnew[base + 4 * t + 0] = 0.0f;
    g_ipnew[base + 4 * t + 1] = 0.0f;
    g_ipnew[base + 4 * t + 2] = 0.0f;
    g_ipnew[base + 4 * t + 3] = 0.0f;
}

// ---------------- tf32 mma.sync GEMM + fused LSTM epilogue ----------------
// CTA: 128 rows x 128 gate-cols. 8 warps (4 M x 2 N), warp tile 32x64.
// K = 256 in 8 chunks of 32. 3-stage all-cp.async pipeline.
// A = raw fp32 (HW tf32 truncation), B = pre-rounded rna tf32 in g_WT.
#define A_STRIDE 36
#define HALF_STAGE (128 * A_STRIDE * 4)          // 18432 (A part)
#define STAGE_BYTES (2 * HALF_STAGE)             // 36864 (A + B)
#define SMEM_TOTAL_GEMM (3 * STAGE_BYTES)        // 110592

__global__ __launch_bounds__(256, 2) void ip_lstm_mma(
    const float* __restrict__ X, int xs,
    const float* __restrict__ Hp, int hs,
    const float* __restrict__ Cold,
    const float* __restrict__ WT, const float* __restrict__ bP,
    float* __restrict__ outC, float* __restrict__ outH)
{
    extern __shared__ char smem[];

    int tid = threadIdx.x;
    int wid = tid >> 5, lane = tid & 31;
    int wm = wid & 3, wn = wid >> 2;          // 4 M-warps x 2 N-warps
    int row0 = blockIdx.y * 128;
    int col0 = blockIdx.x * 128;

    float acc[2][8][4];
#pragma unroll
    for (int mt = 0; mt < 2; mt++)
#pragma unroll
        for (int nt = 0; nt < 8; nt++)
#pragma unroll
            for (int q = 0; q < 4; q++) acc[mt][nt][q] = 0.0f;

    float bI[4], bF[4], bG[4], bO[4];
#pragma unroll
    for (int p = 0; p < 4; p++) {
        int c0 = col0 + wn * 64 + p * 16 + (lane & 3) * 2;
        bI[p] = bP[c0];     bF[p] = bP[c0 + 1];
        bG[p] = bP[c0 + 8]; bO[p] = bP[c0 + 9];
    }

    // per-thread load coords (shared by A and B: 128 rows x 8 float4 each)
    int lr = tid >> 1;                 // base row for j-loop (r = lr + j*... ) — see below
    // we use fid = j*256 + tid; r = fid>>3, q = fid&7

    // prefetch helper (macro-ish lambda)
    auto prefetch = [&](int c) {
        const float* Asrc = (c < 4) ? X : Hp;
        int astr = (c < 4) ? xs : hs;
        int ka = (c & 3) * 32;
        int kb = c * 32;
        char* As = smem + (c % 3) * STAGE_BYTES;
        char* Bs = As + HALF_STAGE;
#pragma unroll
        for (int j = 0; j < 4; j++) {
            int fid = j * 256 + tid;
            int r = fid >> 3, q = fid & 7;
            CP_ASYNC16(smem_u32(As + r * (A_STRIDE * 4) + q * 16),
                       Asrc + (size_t)(row0 + r) * astr + ka + q * 4);
            CP_ASYNC16(smem_u32(Bs + r * (A_STRIDE * 4) + q * 16),
                       WT + (size_t)(col0 + r) * PK + kb + q * 4);
        }
    };

    // prologue: stages 0 and 1 in flight
    prefetch(0); CP_COMMIT();
    prefetch(1); CP_COMMIT();
    CP_WAIT1();
    __syncthreads();

    int a_base = (wm * 32 + (lane >> 2)) * A_STRIDE;
    int b_base = (wn * 64 + (lane >> 2)) * A_STRIDE;
    int kc = lane & 3;

#pragma unroll 1
    for (int ch = 0; ch < 8; ch++) {
        uint32_t* Abuf = (uint32_t*)(smem + (ch % 3) * STAGE_BYTES);
        uint32_t* Bbuf = (uint32_t*)(smem + (ch % 3) * STAGE_BYTES + HALF_STAGE);
#pragma unroll
        for (int ks = 0; ks < 4; ks++) {
            int kk = ks * 8 + kc;
            uint32_t a[2][4];
#pragma unroll
            for (int mt = 0; mt < 2; mt++) {
                int rb = a_base + mt * 16 * A_STRIDE;
                a[mt][0] = Abuf[rb + kk];
                a[mt][1] = Abuf[rb + 8 * A_STRIDE + kk];
                a[mt][2] = Abuf[rb + kk + 4];
                a[mt][3] = Abuf[rb + 8 * A_STRIDE + kk + 4];
            }
            uint32_t b[8][2];
#pragma unroll
            for (int nt = 0; nt < 8; nt++) {
                int nb = b_base + nt * 8 * A_STRIDE;
                b[nt][0] = Bbuf[nb + kk];
                b[nt][1] = Bbuf[nb + kk + 4];
            }
#pragma unroll
            for (int mt = 0; mt < 2; mt++)
#pragma unroll
                for (int nt = 0; nt < 8; nt++)
                    mma8(acc[mt][nt], a[mt], b[nt]);
        }

        if (ch < 7) {
            if (ch < 6) {
                prefetch(ch + 2);
                CP_COMMIT();
                CP_WAIT1();          // ch+1 resident
            } else {
                CP_WAIT0();          // last chunk resident
            }
            __syncthreads();
        }
    }

    // ---- fused LSTM epilogue ----
#pragma unroll
    for (int mt = 0; mt < 2; mt++) {
        int r = row0 + wm * 32 + mt * 16 + (lane >> 2);
#pragma unroll
        for (int p = 0; p < 4; p++) {
            int u = (col0 >> 2) + wn * 16 + p * 4 + (lane & 3);
            float co0 = Cold[(size_t)r * PH + u];
            float co1 = Cold[(size_t)(r + 8) * PH + u];
            float iv = acc[mt][2 * p][0] + bI[p];
            float fv = acc[mt][2 * p][1] + bF[p];
            float gv = acc[mt][2 * p + 1][0] + bG[p];
            float ov = acc[mt][2 * p + 1][1] + bO[p];
            float cn0 = sigf(fv) * co0 + sigf(iv) * tanhf_f(gv);
            float hn0 = sigf(ov) * tanhf_f(cn0);
            float iv1 = acc[mt][2 * p][2] + bI[p];
            float fv1 = acc[mt][2 * p][3] + bF[p];
            float gv1 = acc[mt][2 * p + 1][2] + bG[p];
            float ov1 = acc[mt][2 * p + 1][3] + bO[p];
            float cn1 = sigf(fv1) * co1 + sigf(iv1) * tanhf_f(gv1);
            float hn1 = sigf(ov1) * tanhf_f(cn1);

            outC[(size_t)r * PG4 + u] = cn0;
            outH[(size_t)r * PG4 + u] = hn0;
            outC[(size_t)(r + 8) * PG4 + u] = cn1;
            outH[(size_t)(r + 8) * PG4 + u] = hn1;
        }
    }
}

// ---------------- mask exit/raise nodes: contrib <- old state ----------------
__global__ void ip_mask(const float* __restrict__ hc0, const float* __restrict__ hh0,
                        const float* __restrict__ hc1, const float* __restrict__ hh1,
                        const int* __restrict__ exi, const int* __restrict__ rai)
{
    int b = blockIdx.x;
    int node = blockIdx.y ? rai[b] : exi[b];
    int tid = threadIdx.x;  // 128
    size_t r = (size_t)b * PN + node;
    float* dst = g_contrib + r * PG4;
    size_t rb = r * PH;
    dst[tid]       = hc0[rb + tid];
    dst[128 + tid] = hh0[rb + tid];
    dst[256 + tid] = hc1[rb + tid];
    dst[384 + tid] = hh1[rb + tid];
}

// ---------------- decision heads + CSR edge fill + ip scatter ----------------
__global__ __launch_bounds__(256) void ip_decision(
    const float* __restrict__ Wr, const float* __restrict__ brs,
    const float* __restrict__ Wb, const float* __restrict__ bbs,
    const float* __restrict__ ipin,
    const int* __restrict__ ti, const int* __restrict__ fi, const int* __restrict__ ri,
    const int* __restrict__ exi, const int* __restrict__ rai,
    const int* __restrict__ slim, const int* __restrict__ cstep, int cs_fallback)
{
    __shared__ float sW[2048];  // [0:1024) W_raise, [1024:2048) W_branch
    int tid = threadIdx.x;
    for (int i = tid; i < 1024; i += 256) { sW[i] = Wr[i]; sW[1024 + i] = Wb[i]; }
    __syncthreads();

    int lane = tid & 31;
    int row = blockIdx.x * 8 + (tid >> 5);
    int b = row >> 11, n = row & 2047;

    int cs = cstep ? cstep[0] : cs_fallback;
    if (cs >= slim[b]) return;

    const float* crow = g_contrib + (size_t)row * PG4;
    float4 v[4];
#pragma unroll
    for (int t2 = 0; t2 < 4; t2++) v[t2] = *(const float4*)&crow[lane * 4 + t2 * 128];

    float r0 = 0.f, r1 = 0.f, q0 = 0.f, q1 = 0.f;
#pragma unroll
    for (int t2 = 0; t2 < 4; t2++) {
        int cb = lane * 4 + t2 * 128;
        float vv[4] = {v[t2].x, v[t2].y, v[t2].z, v[t2].w};
#pragma unroll
        for (int q = 0; q < 4; q++) {
            float w = vv[q];
            int c2 = (cb + q) * 2;
            r0 = fmaf(w, sW[c2 + 0], r0);
            r1 = fmaf(w, sW[c2 + 1], r1);
            q0 = fmaf(w, sW[1024 + c2 + 0], q0);
            q1 = fmaf(w, sW[1024 + c2 + 1], q1);
        }
    }
#pragma unroll
    for (int o = 16; o > 0; o >>= 1) {
        r0 += __shfl_xor_sync(0xffffffffu, r0, o);
        r1 += __shfl_xor_sync(0xffffffffu, r1, o);
        q0 += __shfl_xor_sync(0xffffffffu, q0, o);
        q1 += __shfl_xor_sync(0xffffffffu, q1, o);
    }

    float lr = (r0 + brs[0]) - (r1 + brs[1]);
    float p_raise = 1.0f / (1.0f + expf(-lr));
    float p_no = 1.0f - p_raise;
    if (n == exi[b] || n == rai[b]) { p_raise = 0.0f; p_no = 1.0f; }
    float lb = (q0 + bbs[0]) - (q1 + bbs[1]);
    float pb0 = 1.0f / (1.0f + expf(-lb));
    float pb1 = 1.0f - pb0;

    float ipv = ipin[row];
    float wr_ = p_raise * ipv;
    float wt_ = p_no * pb0 * ipv;
    float wf_ = p_no * pb1 * ipv;

    if (lane == 0) {
        int bb2 = b << 11;
        int tr = bb2 + ri[row], tt = bb2 + ti[row], tf = bb2 + fi[row];
        atomicAdd(&g_ipnew[tr], wr_);
        atomicAdd(&g_ipnew[tt], wt_);
        atomicAdd(&g_ipnew[tf], wf_);
        if (wr_ != 0.0f) {
            int s = atomicAdd(&g_cur[tr], 1);
            g_esrc[s] = row; g_ew[s] = wr_;
        }
        if (wt_ != 0.0f) {
            int s = atomicAdd(&g_cur[tt], 1);
            g_esrc[s] = row; g_ew[s] = wt_;
        }
        if (wf_ != 0.0f) {
            int s = atomicAdd(&g_cur[tf], 1);
            g_esrc[s] = row; g_ew[s] = wf_;
        }
    }
}

// ---------------- gather + finalize: one pass, no atomics, no accum ----------
__global__ __launch_bounds__(128) void ip_gather(
    const float* __restrict__ hc0, const float* __restrict__ hh0,
    const float* __restrict__ hc1, const float* __restrict__ hh1,
    const float* __restrict__ ipold, const int* __restrict__ slim,
    const int* __restrict__ cstep, int cs_fallback, float* __restrict__ out)
{
    int row = blockIdx.x;
    int tid = threadIdx.x;  // 128
    int b = row >> 11;
    int cs = cstep ? cstep[0] : cs_fallback;
    bool nd = cs < slim[b];
    size_t ob = (size_t)row * 513;
    if (nd) {
        int s = g_off[row], e = g_cur[row];
        const float4* cb = (const float4*)g_contrib;
        float ax = 0.f, ay = 0.f, az = 0.f, aw = 0.f;
        for (int i = s; i < e; i++) {
            float w = g_ew[i];
            int src = g_esrc[i];
            float4 v = cb[(size_t)src * 128 + tid];
            ax = fmaf(w, v.x, ax); ay = fmaf(w, v.y, ay);
            az = fmaf(w, v.z, az); aw = fmaf(w, v.w, aw);
        }
        float ipn = g_ipnew[row];
        float inv = __fdividef(1.0f, ipn + 1e-7f);
        out[ob + 4 * tid + 0] = ax * inv;
        out[ob + 4 * tid + 1] = ay * inv;
        out[ob + 4 * tid + 2] = az * inv;
        out[ob + 4 * tid + 3] = aw * inv;
        if (tid == 0) out[ob + 512] = ipn;
    } else {
        size_t rb = (size_t)row * PH;
        out[ob + tid]       = hc0[rb + tid];
        out[ob + 128 + tid] = hh0[rb + tid];
        out[ob + 256 + tid] = hc1[rb + tid];
        out[ob + 384 + tid] = hh1[rb + tid];
        if (tid == 0) out[ob + 512] = ipold[row];
    }
}

// ---------------- host launcher ----------------
extern "C" void kernel_launch(void* const* d_in, const int* in_sizes, int n_in,
                              void* d_out, int out_size)
{
    const float* emb  = (const float*)d_in[0];
    const float* hc0  = (const float*)d_in[1];
    const float* hh0  = (const float*)d_in[2];
    const float* hc1  = (const float*)d_in[3];
    const float* hh1  = (const float*)d_in[4];
    const float* ip   = (const float*)d_in[5];
    const float* Wi0  = (const float*)d_in[6];
    const float* Wh0  = (const float*)d_in[7];
    const float* b0   = (const float*)d_in[8];
    const float* Wi1  = (const float*)d_in[9];
    const float* Wh1  = (const float*)d_in[10];
    const float* b1   = (const float*)d_in[11];
    const float* Wr   = (const float*)d_in[12];
    const float* br   = (const float*)d_in[13];
    const float* Wb   = (const float*)d_in[14];
    const float* bb   = (const float*)d_in[15];
    const int* ti     = (const int*)d_in[16];
    const int* fi     = (const int*)d_in[17];
    const int* ri     = (const int*)d_in[18];
    const int* exi    = (const int*)d_in[19];
    const int* rai    = (const int*)d_in[20];
    const int* slim   = (const int*)d_in[21];
    const int* cstep  = (n_in >= 23) ? (const int*)d_in[22] : nullptr;
    float* out = (float*)d_out;

    float *contrib, *WT0, *WT1;
    int* cnt;
    cudaGetSymbolAddress((void**)&contrib, g_contrib);
    cudaGetSymbolAddress((void**)&WT0,     g_WT0);
    cudaGetSymbolAddress((void**)&WT1,     g_WT1);
    cudaGetSymbolAddress((void**)&cnt,     g_cnt);

    cudaFuncSetAttribute(ip_lstm_mma,
                         cudaFuncAttributeMaxDynamicSharedMemorySize, SMEM_TOTAL_GEMM);

    cudaMemsetAsync(cnt, 0, sizeof(int) * (size_t)PM, 0);
    ip_count<<<PM / 256, 256>>>(ti, fi, ri);
    ip_permW<<<512, 256>>>(Wi0, Wh0, WT0);
    ip_permW<<<512, 256>>>(Wi1, Wh1, WT1);
    ip_permB<<<2, 256>>>(b0, b1);

    dim3 ggrid(4, PM / 128);
    // Layer 0
    ip_lstm_mma<<<ggrid, 256, SMEM_TOTAL_GEMM>>>(
        emb, PH, hh0, PH, hc0, WT0, g_bP0, contrib + 0, contrib + 128);
    // Layer 1
    ip_lstm_mma<<<ggrid, 256, SMEM_TOTAL_GEMM>>>(
        contrib + 128, PG4, hh1, PH, hc1, WT1, g_bP1, contrib + 256, contrib + 384);

    ip_scan<<<PB, 512>>>();

    ip_mask<<<dim3(PB, 2), 128>>>(hc0, hh0, hc1, hh1, exi, rai);

    ip_decision<<<PM / 8, 256>>>(Wr, br, Wb, bb, ip, ti, fi, ri, exi, rai,
                                 slim, cstep, 5);

    ip_gather<<<PM, 128>>>(hc0, hh0, hc1, hh1, ip, slim, cstep, 5, out);
}